// round 4
// baseline (speedup 1.0000x reference)
#include <cuda_runtime.h>
#include <math.h>

#define BQ   2048     // total agents (B)
#define HD   64
#define ATTD 1024
#define PADK 80       // 68 padded to multiple of 16

typedef unsigned long long ull;

// ---------------- packed f32x2 helpers ----------------
__device__ __forceinline__ void ffma2(ull& d, ull a, ull b) {
    asm("fma.rn.f32x2 %0, %1, %2, %0;" : "+l"(d) : "l"(a), "l"(b));
}
__device__ __forceinline__ float2 f2unpack(ull v) {
    float2 r; asm("mov.b64 {%0, %1}, %2;" : "=f"(r.x), "=f"(r.y) : "l"(v)); return r;
}
// ---------------- cp.async helpers ----------------
__device__ __forceinline__ void cpasync16(void* smem, const void* g) {
    unsigned sa = (unsigned)__cvta_generic_to_shared(smem);
    asm volatile("cp.async.cg.shared.global [%0], [%1], 16;" :: "r"(sa), "l"(g));
}
__device__ __forceinline__ void cp_commit() { asm volatile("cp.async.commit_group;"); }
__device__ __forceinline__ void cp_wait0()  { asm volatile("cp.async.wait_group 0;"); }

// ---------------- device scratch ----------------
__device__ float g_dec[BQ * ATTD];
__device__ float g_encR[(size_t)BQ * 64 * HD];
__device__ int   g_rowb[BQ * 64];
__device__ int   g_base[BQ];
__device__ int   g_nnz[BQ];
__device__ float g_scoreR[BQ * 64];
__device__ int   g_R;
__device__ float g_empty[BQ];                 // empty-cell score numerator per anchor
__device__ float g_ctxemb[BQ * PADK];
__device__ float g_WoutP[PADK * ATTD];
__device__ float g_out[BQ * ATTD];
__device__ float g_x[BQ * ATTD];
__device__ float g_bnsum[ATTD];
__device__ float g_bnsum2[ATTD];
__device__ float g_bna[ATTD];
__device__ float g_bnb[ATTD];

// ---------------- prep: pad W_out + zero counters ----------------
__global__ void k_prep(const float* __restrict__ Wout) {
    int idx = blockIdx.x * blockDim.x + threadIdx.x;
    if (idx < PADK * ATTD) g_WoutP[idx] = ((idx >> 10) < 68) ? Wout[idx] : 0.f;
    if (idx < ATTD) { g_bnsum[idx] = 0.f; g_bnsum2[idx] = 0.f; }
    if (idx < BQ) g_empty[idx] = 0.f;
    if (idx == 0) g_R = 0;
}

// ---------------- social pooling + compaction (256 thr/anchor) ----------------
__global__ void k_pool(const float* __restrict__ h, const float* __restrict__ end_pos) {
    int b = blockIdx.x;
    int s = b >> 6;
    int i = b & 63;
    int tid = threadIdx.x;      // 256
    int d = tid & 63;           // hidden dim
    int g = tid >> 6;           // j-group 0..3

    __shared__ __align__(16) float hsh[4096];
    __shared__ __align__(16) float acc[4096];
    __shared__ float px[64], py[64];
    __shared__ int   cellj[64];
    __shared__ int   nz[64];
    __shared__ int   slot_cell[64];
    __shared__ int   sh_base, sh_n;

    for (int t = tid; t < 1024; t += 256) {
        *(float4*)&hsh[t * 4] = *(const float4*)(h + (size_t)s * 4096 + t * 4);
        *(float4*)&acc[t * 4] = make_float4(0.f, 0.f, 0.f, 0.f);
    }
    if (tid < 64) {
        px[tid] = end_pos[(s * 64 + tid) * 2 + 0];
        py[tid] = end_pos[(s * 64 + tid) * 2 + 1];
        nz[tid] = 0;
    }
    __syncthreads();

    if (tid < 64) {
        float ax = px[i], ay = py[i];
        float tlx = ax - 1.0f, tly = ay + 1.0f;
        float brx = ax + 1.0f, bry = ay - 1.0f;
        float ox = px[tid], oy = py[tid];
        bool oob = (ox >= brx) || (ox <= tlx) || (oy >= tly) || (oy <= bry) || (tid == i);
        int c = -1;
        if (!oob) {
            float cx = floorf((ox - tlx) / 2.0f * 8.0f);
            float cy = floorf((tly - oy) / 2.0f * 8.0f);
            c = (int)(cx + cy * 8.0f);
        }
        cellj[tid] = c;
    }
    __syncthreads();

    for (int j = g * 16; j < g * 16 + 16; j++) {
        int c = cellj[j];
        if (c >= 0) {
            atomicAdd(&acc[c * 64 + d], hsh[j * 64 + d]);
            if (d == 0) nz[c] = 1;
        }
    }
    __syncthreads();

    if (tid == 0) {
        int n = 0;
        for (int c = 0; c < 64; c++) if (nz[c]) slot_cell[n++] = c;
        int base = atomicAdd(&g_R, n);
        sh_base = base; sh_n = n;
        g_base[b] = base; g_nnz[b] = n;
    }
    __syncthreads();

    int base = sh_base, n = sh_n;
    for (int t = g; t < n; t += 4) {
        int c = slot_cell[t];
        g_encR[(size_t)(base + t) * 64 + d] = acc[c * 64 + d];
        if (d == 0) g_rowb[base + t] = b;
    }
}

// ---------------- pipelined fp32x2 SGEMM with duplicated-A smem --------------
// C = act(A[M,K]@B[K,N] + bias); 128x128 tile, 256 thr, 2-stage, 8x8 micro.
// A is stored duplicated in smem: As[st][k][2r..2r+1] = (a, a) so FFMA2 gets
// its replicated operand from a broadcast LDS.128 (no MOV-pair building).
// EMPTY: additionally accumulate relu(C + benc).wfull per row into empty_out.
template<int RELU, int EMPTY>
__global__ void __launch_bounds__(256) k_sgemm(const float* __restrict__ A,
                                               const float* __restrict__ B,
                                               const float* __restrict__ bias,
                                               float* __restrict__ C,
                                               int N, int K,
                                               const float* __restrict__ benc,
                                               const float* __restrict__ wfull,
                                               float* __restrict__ empty_out) {
    extern __shared__ float sm[];
    float (*As)[16][256] = (float(*)[16][256])sm;              // 2 stages, dup rows
    float (*Bs)[16][128] = (float(*)[16][128])(sm + 2 * 16 * 256);
    int tid = threadIdx.x;
    int m0 = blockIdx.y * 128;
    int n0 = blockIdx.x * 128;
    int tr = tid >> 4, tc = tid & 15;
    int KT = K >> 4;

    float4 areg[2];
    auto ldgA = [&](int k0) {
#pragma unroll
        for (int q = 0; q < 2; q++) {
            int c = tid + q * 256;
            areg[q] = *(const float4*)(A + (size_t)(m0 + (c >> 2)) * K + k0 + (c & 3) * 4);
        }
    };
    auto stsA = [&](int st) {
#pragma unroll
        for (int q = 0; q < 2; q++) {
            int c = tid + q * 256;
            int row = c >> 2, kq = (c & 3) * 4;
            *(float2*)&As[st][kq + 0][2 * row] = make_float2(areg[q].x, areg[q].x);
            *(float2*)&As[st][kq + 1][2 * row] = make_float2(areg[q].y, areg[q].y);
            *(float2*)&As[st][kq + 2][2 * row] = make_float2(areg[q].z, areg[q].z);
            *(float2*)&As[st][kq + 3][2 * row] = make_float2(areg[q].w, areg[q].w);
        }
    };
    auto ldB = [&](int st, int k0) {
#pragma unroll
        for (int q = 0; q < 2; q++) {
            int c = tid + q * 256;
            int bk = c >> 5, bc = (c & 31) * 4;
            cpasync16(&Bs[st][bk][bc], B + (size_t)(k0 + bk) * N + n0 + bc);
        }
    };

    ull acc[8][4];
#pragma unroll
    for (int i = 0; i < 8; i++)
#pragma unroll
        for (int j = 0; j < 4; j++) acc[i][j] = 0ull;

    ldgA(0); ldB(0, 0); cp_commit();

    for (int it = 0; it < KT; it++) {
        int cur = it & 1;
        stsA(cur);
        cp_wait0();
        __syncthreads();
        if (it + 1 < KT) { ldgA((it + 1) * 16); ldB(cur ^ 1, (it + 1) * 16); }
        cp_commit();

#pragma unroll
        for (int k = 0; k < 16; k++) {
            ulonglong2 qa0 = *(ulonglong2*)&As[cur][k][8 * tr];
            ulonglong2 qa1 = *(ulonglong2*)&As[cur][k][8 * tr + 4];
            ulonglong2 qa2 = *(ulonglong2*)&As[cur][k][128 + 8 * tr];
            ulonglong2 qa3 = *(ulonglong2*)&As[cur][k][128 + 8 * tr + 4];
            ulonglong2 b0 = *(ulonglong2*)&Bs[cur][k][tc * 4];
            ulonglong2 b1 = *(ulonglong2*)&Bs[cur][k][64 + tc * 4];
            ffma2(acc[0][0], qa0.x, b0.x); ffma2(acc[0][1], qa0.x, b0.y); ffma2(acc[0][2], qa0.x, b1.x); ffma2(acc[0][3], qa0.x, b1.y);
            ffma2(acc[1][0], qa0.y, b0.x); ffma2(acc[1][1], qa0.y, b0.y); ffma2(acc[1][2], qa0.y, b1.x); ffma2(acc[1][3], qa0.y, b1.y);
            ffma2(acc[2][0], qa1.x, b0.x); ffma2(acc[2][1], qa1.x, b0.y); ffma2(acc[2][2], qa1.x, b1.x); ffma2(acc[2][3], qa1.x, b1.y);
            ffma2(acc[3][0], qa1.y, b0.x); ffma2(acc[3][1], qa1.y, b0.y); ffma2(acc[3][2], qa1.y, b1.x); ffma2(acc[3][3], qa1.y, b1.y);
            ffma2(acc[4][0], qa2.x, b0.x); ffma2(acc[4][1], qa2.x, b0.y); ffma2(acc[4][2], qa2.x, b1.x); ffma2(acc[4][3], qa2.x, b1.y);
            ffma2(acc[5][0], qa2.y, b0.x); ffma2(acc[5][1], qa2.y, b0.y); ffma2(acc[5][2], qa2.y, b1.x); ffma2(acc[5][3], qa2.y, b1.y);
            ffma2(acc[6][0], qa3.x, b0.x); ffma2(acc[6][1], qa3.x, b0.y); ffma2(acc[6][2], qa3.x, b1.x); ffma2(acc[6][3], qa3.x, b1.y);
            ffma2(acc[7][0], qa3.y, b0.x); ffma2(acc[7][1], qa3.y, b0.y); ffma2(acc[7][2], qa3.y, b1.x); ffma2(acc[7][3], qa3.y, b1.y);
        }
        __syncthreads();
    }

    float4 bv0 = *(const float4*)(bias + n0 + tc * 4);
    float4 bv1 = *(const float4*)(bias + n0 + 64 + tc * 4);
    float4 be0 = make_float4(0.f, 0.f, 0.f, 0.f), be1 = be0, wf0 = be0, wf1 = be0;
    if (EMPTY) {
        be0 = *(const float4*)(benc + n0 + tc * 4);
        be1 = *(const float4*)(benc + n0 + 64 + tc * 4);
        wf0 = *(const float4*)(wfull + n0 + tc * 4);
        wf1 = *(const float4*)(wfull + n0 + 64 + tc * 4);
    }
#pragma unroll
    for (int i = 0; i < 8; i++) {
        int m = m0 + ((i < 4) ? (tr * 4 + i) : (64 + tr * 4 + i - 4));
        float2 p0 = f2unpack(acc[i][0]);
        float2 p1 = f2unpack(acc[i][1]);
        float2 p2 = f2unpack(acc[i][2]);
        float2 p3 = f2unpack(acc[i][3]);
        float4 o0 = make_float4(p0.x + bv0.x, p0.y + bv0.y, p1.x + bv0.z, p1.y + bv0.w);
        float4 o1 = make_float4(p2.x + bv1.x, p2.y + bv1.y, p3.x + bv1.z, p3.y + bv1.w);
        if (RELU) {
            o0.x = fmaxf(o0.x, 0.f); o0.y = fmaxf(o0.y, 0.f); o0.z = fmaxf(o0.z, 0.f); o0.w = fmaxf(o0.w, 0.f);
            o1.x = fmaxf(o1.x, 0.f); o1.y = fmaxf(o1.y, 0.f); o1.z = fmaxf(o1.z, 0.f); o1.w = fmaxf(o1.w, 0.f);
        }
        *(float4*)(C + (size_t)m * N + n0 + tc * 4)      = o0;
        *(float4*)(C + (size_t)m * N + n0 + 64 + tc * 4) = o1;
        if (EMPTY) {
            float r = 0.f, v;
            v = o0.x + be0.x; if (v > 0.f) r += v * wf0.x;
            v = o0.y + be0.y; if (v > 0.f) r += v * wf0.y;
            v = o0.z + be0.z; if (v > 0.f) r += v * wf0.z;
            v = o0.w + be0.w; if (v > 0.f) r += v * wf0.w;
            v = o1.x + be1.x; if (v > 0.f) r += v * wf1.x;
            v = o1.y + be1.y; if (v > 0.f) r += v * wf1.y;
            v = o1.z + be1.z; if (v > 0.f) r += v * wf1.z;
            v = o1.w + be1.w; if (v > 0.f) r += v * wf1.w;
            r += __shfl_xor_sync(0xffffffffu, r, 1);
            r += __shfl_xor_sync(0xffffffffu, r, 2);
            r += __shfl_xor_sync(0xffffffffu, r, 4);
            r += __shfl_xor_sync(0xffffffffu, r, 8);
            if (tc == 0) atomicAdd(&empty_out[m], r);
        }
    }
}

// ---------------- fused sparse score GEMM (dup-A, pipelined) -----------------
// score[r] = sum_a relu(enc_r . Wenc[:,a] + benc[a] + dec[rowb[r],a]) * wfull[a] + bfull
__global__ void __launch_bounds__(256) k_scores(const float* __restrict__ Wenc,
                                                const float* __restrict__ benc,
                                                const float* __restrict__ wfull,
                                                const float* __restrict__ bfull) {
    int R = g_R;
    int r0 = blockIdx.x * 64;
    if (r0 >= R) return;

    extern __shared__ float sm[];
    float (*As)[128]      = (float(*)[128])sm;                 // [64 k][128 dup rows]
    float (*Bs)[16][128]  = (float(*)[16][128])(sm + 64 * 128);

    int tid = threadIdx.x;  // 256
    int tr = tid >> 4, tc = tid & 15;
    float bf0 = bfull[0];

    // A fill (dup): warp-consecutive rows -> 2-way STS at worst
#pragma unroll
    for (int it = 0; it < 4; it++) {
        int c = tid + it * 256;       // 0..1023
        int row = c & 63;
        int kq = (c >> 6) * 4;
        float4 v = make_float4(0.f, 0.f, 0.f, 0.f);
        if (r0 + row < R) v = *(const float4*)(g_encR + (size_t)(r0 + row) * 64 + kq);
        *(float2*)&As[kq + 0][2 * row] = make_float2(v.x, v.x);
        *(float2*)&As[kq + 1][2 * row] = make_float2(v.y, v.y);
        *(float2*)&As[kq + 2][2 * row] = make_float2(v.z, v.z);
        *(float2*)&As[kq + 3][2 * row] = make_float2(v.w, v.w);
    }
    int brow[4];
#pragma unroll
    for (int i = 0; i < 4; i++) {
        int rr = r0 + tr * 4 + i;
        brow[i] = (rr < R) ? g_rowb[rr] : 0;
    }

    auto stage_load = [&](int st, int t) {
        int ks = t & 3, ct = t >> 2;
#pragma unroll
        for (int q = 0; q < 2; q++) {
            int c = tid + q * 256;
            int kr = c >> 5, cc = (c & 31) * 4;
            cpasync16(&Bs[st][kr][cc], Wenc + (size_t)(ks * 16 + kr) * 1024 + ct * 128 + cc);
        }
    };

    float rowsum[4] = {0.f, 0.f, 0.f, 0.f};
    ull acc[4][4];

    stage_load(0, 0);
    cp_commit();

    for (int t = 0; t < 32; t++) {
        int cur = t & 1;
        int ks = t & 3, ct = t >> 2;
        cp_wait0();
        __syncthreads();
        if (t + 1 < 32) stage_load(cur ^ 1, t + 1);
        cp_commit();

        if (ks == 0) {
#pragma unroll
            for (int i = 0; i < 4; i++)
#pragma unroll
                for (int j = 0; j < 4; j++) acc[i][j] = 0ull;
        }

#pragma unroll
        for (int k = 0; k < 16; k++) {
            int kk = ks * 16 + k;
            ulonglong2 qa0 = *(ulonglong2*)&As[kk][8 * tr];
            ulonglong2 qa1 = *(ulonglong2*)&As[kk][8 * tr + 4];
            ulonglong2 b0 = *(ulonglong2*)&Bs[cur][k][tc * 4];
            ulonglong2 b1 = *(ulonglong2*)&Bs[cur][k][64 + tc * 4];
            ffma2(acc[0][0], qa0.x, b0.x); ffma2(acc[0][1], qa0.x, b0.y); ffma2(acc[0][2], qa0.x, b1.x); ffma2(acc[0][3], qa0.x, b1.y);
            ffma2(acc[1][0], qa0.y, b0.x); ffma2(acc[1][1], qa0.y, b0.y); ffma2(acc[1][2], qa0.y, b1.x); ffma2(acc[1][3], qa0.y, b1.y);
            ffma2(acc[2][0], qa1.x, b0.x); ffma2(acc[2][1], qa1.x, b0.y); ffma2(acc[2][2], qa1.x, b1.x); ffma2(acc[2][3], qa1.x, b1.y);
            ffma2(acc[3][0], qa1.y, b0.x); ffma2(acc[3][1], qa1.y, b0.y); ffma2(acc[3][2], qa1.y, b1.x); ffma2(acc[3][3], qa1.y, b1.y);
        }

        if (ks == 3) {
            int n0 = ct * 128;
            float4 be0 = *(const float4*)(benc + n0 + tc * 4);
            float4 be1 = *(const float4*)(benc + n0 + 64 + tc * 4);
            float4 wf0 = *(const float4*)(wfull + n0 + tc * 4);
            float4 wf1 = *(const float4*)(wfull + n0 + 64 + tc * 4);
#pragma unroll
            for (int i = 0; i < 4; i++) {
                const float* decrow = g_dec + (size_t)brow[i] * 1024 + n0;
                float4 d0 = *(const float4*)(decrow + tc * 4);
                float4 d1 = *(const float4*)(decrow + 64 + tc * 4);
                float2 p0 = f2unpack(acc[i][0]);
                float2 p1 = f2unpack(acc[i][1]);
                float2 p2 = f2unpack(acc[i][2]);
                float2 p3 = f2unpack(acc[i][3]);
                float rs = 0.f, v;
                v = p0.x + be0.x + d0.x; if (v > 0.f) rs += v * wf0.x;
                v = p0.y + be0.y + d0.y; if (v > 0.f) rs += v * wf0.y;
                v = p1.x + be0.z + d0.z; if (v > 0.f) rs += v * wf0.z;
                v = p1.y + be0.w + d0.w; if (v > 0.f) rs += v * wf0.w;
                v = p2.x + be1.x + d1.x; if (v > 0.f) rs += v * wf1.x;
                v = p2.y + be1.y + d1.y; if (v > 0.f) rs += v * wf1.y;
                v = p3.x + be1.z + d1.z; if (v > 0.f) rs += v * wf1.z;
                v = p3.y + be1.w + d1.w; if (v > 0.f) rs += v * wf1.w;
                rowsum[i] += rs;
            }
        }
    }

#pragma unroll
    for (int i = 0; i < 4; i++) {
        float r = rowsum[i];
        r += __shfl_xor_sync(0xffffffffu, r, 1);
        r += __shfl_xor_sync(0xffffffffu, r, 2);
        r += __shfl_xor_sync(0xffffffffu, r, 4);
        r += __shfl_xor_sync(0xffffffffu, r, 8);
        int rr = r0 + tr * 4 + i;
        if (tc == 0 && rr < R) g_scoreR[rr] = r + bf0;
    }
}

// ---------------- softmax + ctx + embed (64 thr/anchor) ----------------
__global__ void k_softctx(const float* __restrict__ bfull, const float* __restrict__ end_pos,
                          const float* __restrict__ rel_pos, const float* __restrict__ Wemb,
                          const float* __restrict__ bemb) {
    int b = blockIdx.x;
    int tid = threadIdx.x;  // 64
    __shared__ float sc[64];
    __shared__ float alpha[64];

    int base = g_base[b], nnz = g_nnz[b];
    if (tid < nnz) sc[tid] = g_scoreR[base + tid];
    __syncthreads();
    if (tid == 0) {
        float se = g_empty[b] + bfull[0];
        float m = se;
        for (int t = 0; t < nnz; t++) m = fmaxf(m, sc[t]);
        float Z = (float)(64 - nnz) * expf(se - m);
        for (int t = 0; t < nnz; t++) { float e = expf(sc[t] - m); alpha[t] = e; Z += e; }
        float inv = 1.0f / Z;
        for (int t = 0; t < nnz; t++) alpha[t] *= inv;
    }
    __syncthreads();

    float c = 0.f;
    for (int t = 0; t < nnz; t++) c += alpha[t] * g_encR[(size_t)(base + t) * 64 + tid];
    g_ctxemb[b * PADK + tid] = c;

    if (tid < 4) {
        float v = end_pos[b * 2 + 0] * Wemb[0 * 4 + tid] + end_pos[b * 2 + 1] * Wemb[1 * 4 + tid]
                + rel_pos[b * 2 + 0] * Wemb[2 * 4 + tid] + rel_pos[b * 2 + 1] * Wemb[3 * 4 + tid]
                + bemb[tid];
        g_ctxemb[b * PADK + 64 + tid] = v > 0.f ? v : 0.f;
    } else if (tid < 16) {
        g_ctxemb[b * PADK + 64 + tid] = 0.f;
    }
}

// ---------------- batchnorm: partial sums + final + apply --------
__global__ void k_bnpart() {
    int bc = blockIdx.x & 15;
    int rs = blockIdx.x >> 4;
    int c = bc * 64 + (threadIdx.x & 63);
    int rg = threadIdx.x >> 6;
    float s = 0.f, s2 = 0.f;
    for (int r = rs * 256 + rg; r < (rs + 1) * 256; r += 4) {
        float v = g_x[(size_t)r * ATTD + c];
        s += v; s2 += v * v;
    }
    __shared__ float ss[4][64], ss2[4][64];
    ss[rg][threadIdx.x & 63] = s; ss2[rg][threadIdx.x & 63] = s2;
    __syncthreads();
    if (rg == 0) {
        int l = threadIdx.x & 63;
        float t  = ss[0][l] + ss[1][l] + ss[2][l] + ss[3][l];
        float t2 = ss2[0][l] + ss2[1][l] + ss2[2][l] + ss2[3][l];
        atomicAdd(&g_bnsum[c], t);
        atomicAdd(&g_bnsum2[c], t2);
    }
}

__global__ void k_bnfinal(const float* __restrict__ gamma, const float* __restrict__ beta) {
    int c = threadIdx.x;
    float mu = g_bnsum[c] / (float)BQ;
    float var = g_bnsum2[c] / (float)BQ - mu * mu;
    float rstd = rsqrtf(var + 1e-5f);
    float ga = gamma[c] * rstd;
    g_bna[c] = ga;
    g_bnb[c] = beta[c] - mu * ga;
}

__global__ void k_bnapply(float* __restrict__ out) {
    int idx = blockIdx.x * blockDim.x + threadIdx.x;
    if (idx < BQ * ATTD) {
        int c = idx & 1023;
        float v = g_x[idx] * g_bna[c] + g_bnb[c];
        out[idx] = v > 0.f ? v : 0.f;
    }
}

// ---------------- launch ----------------
extern "C" void kernel_launch(void* const* d_in, const int* in_sizes, int n_in,
                              void* d_out, int out_size) {
    const float* h       = (const float*)d_in[0];
    const float* end_pos = (const float*)d_in[2];
    const float* rel_pos = (const float*)d_in[3];
    const float* Wenc    = (const float*)d_in[4];
    const float* benc    = (const float*)d_in[5];
    const float* Wdec    = (const float*)d_in[6];
    const float* bdec    = (const float*)d_in[7];
    const float* wfull   = (const float*)d_in[8];
    const float* bfull   = (const float*)d_in[9];
    const float* Wemb    = (const float*)d_in[10];
    const float* bemb    = (const float*)d_in[11];
    const float* Wout    = (const float*)d_in[12];
    const float* bout    = (const float*)d_in[13];
    const float* Wmlp    = (const float*)d_in[14];
    const float* bmlp    = (const float*)d_in[15];
    const float* gamma   = (const float*)d_in[16];
    const float* beta    = (const float*)d_in[17];
    float* out = (float*)d_out;

    float *p_dec, *p_ctxemb, *p_WoutP, *p_out, *p_x, *p_empty;
    cudaGetSymbolAddress((void**)&p_dec,    g_dec);
    cudaGetSymbolAddress((void**)&p_ctxemb, g_ctxemb);
    cudaGetSymbolAddress((void**)&p_WoutP,  g_WoutP);
    cudaGetSymbolAddress((void**)&p_out,    g_out);
    cudaGetSymbolAddress((void**)&p_x,      g_x);
    cudaGetSymbolAddress((void**)&p_empty,  g_empty);

    dim3 gg(ATTD / 128, BQ / 128);   // (8, 16) = 128 blocks
    const int SMEM = 49152;          // exactly the no-opt-in limit

    k_prep<<<(PADK * ATTD + 255) / 256, 256>>>(Wout);
    k_pool<<<BQ, 256>>>(h, end_pos);
    k_sgemm<0, 1><<<gg, 256, SMEM>>>(h, Wdec, bdec, p_dec, ATTD, HD, benc, wfull, p_empty);
    k_scores<<<BQ, 256, SMEM>>>(Wenc, benc, wfull, bfull);
    k_softctx<<<BQ, 64>>>(bfull, end_pos, rel_pos, Wemb, bemb);
    k_sgemm<1, 0><<<gg, 256, SMEM>>>(p_ctxemb, p_WoutP, bout, p_out, ATTD, PADK, nullptr, nullptr, nullptr);
    k_sgemm<0, 0><<<gg, 256, SMEM>>>(p_out, Wmlp, bmlp, p_x, ATTD, ATTD, nullptr, nullptr, nullptr);
    k_bnpart<<<128, 256>>>();
    k_bnfinal<<<1, 1024>>>(gamma, beta);
    k_bnapply<<<(BQ * ATTD + 255) / 256, 256>>>(out);
}

// round 5
// speedup vs baseline: 1.0871x; 1.0871x over previous
#include <cuda_runtime.h>
#include <math.h>

#define BQ   2048     // total agents (B)
#define HD   64
#define ATTD 1024
#define PADK 80       // 68 padded to multiple of 16

typedef unsigned long long ull;

// ---------------- packed f32x2 helpers ----------------
__device__ __forceinline__ void ffma2(ull& d, ull a, ull b) {
    asm("fma.rn.f32x2 %0, %1, %2, %0;" : "+l"(d) : "l"(a), "l"(b));
}
__device__ __forceinline__ ull f2rep(float x) {
    ull r; asm("mov.b64 %0, {%1, %1};" : "=l"(r) : "f"(x)); return r;
}
__device__ __forceinline__ float2 f2unpack(ull v) {
    float2 r; asm("mov.b64 {%0, %1}, %2;" : "=f"(r.x), "=f"(r.y) : "l"(v)); return r;
}
// ---------------- cp.async helpers ----------------
__device__ __forceinline__ void cpasync16(void* smem, const void* g) {
    unsigned sa = (unsigned)__cvta_generic_to_shared(smem);
    asm volatile("cp.async.cg.shared.global [%0], [%1], 16;" :: "r"(sa), "l"(g));
}
__device__ __forceinline__ void cp_commit() { asm volatile("cp.async.commit_group;"); }
__device__ __forceinline__ void cp_wait0()  { asm volatile("cp.async.wait_group 0;"); }

// ---------------- device scratch ----------------
__device__ float g_dec[BQ * ATTD];
__device__ float g_encR[(size_t)BQ * 64 * HD];
__device__ int   g_rowb[BQ * 64];
__device__ int   g_base[BQ];
__device__ int   g_nnz[BQ];
__device__ float g_scoreR[BQ * 64];
__device__ int   g_R;
__device__ float g_empty[BQ];
__device__ float g_ctxemb[BQ * PADK];
__device__ float g_WoutP[PADK * ATTD];
__device__ float g_out[BQ * ATTD];
__device__ float g_x[BQ * ATTD];
__device__ float g_bnsum[ATTD];
__device__ float g_bnsum2[ATTD];
__device__ float g_bna[ATTD];
__device__ float g_bnb[ATTD];

// ---------------- prep: pad W_out + zero counters ----------------
__global__ void k_prep(const float* __restrict__ Wout) {
    int idx = blockIdx.x * blockDim.x + threadIdx.x;
    if (idx < PADK * ATTD) g_WoutP[idx] = ((idx >> 10) < 68) ? Wout[idx] : 0.f;
    if (idx < ATTD) { g_bnsum[idx] = 0.f; g_bnsum2[idx] = 0.f; }
    if (idx < BQ) g_empty[idx] = 0.f;
    if (idx == 0) g_R = 0;
}

// ---------------- social pooling + compaction (256 thr/anchor) ----------------
__global__ void k_pool(const float* __restrict__ h, const float* __restrict__ end_pos) {
    int b = blockIdx.x;
    int s = b >> 6;
    int i = b & 63;
    int tid = threadIdx.x;      // 256
    int d = tid & 63;
    int g = tid >> 6;

    __shared__ __align__(16) float hsh[4096];
    __shared__ __align__(16) float acc[4096];
    __shared__ float px[64], py[64];
    __shared__ int   cellj[64];
    __shared__ int   nz[64];
    __shared__ int   slot_cell[64];
    __shared__ int   sh_base, sh_n;

    for (int t = tid; t < 1024; t += 256) {
        *(float4*)&hsh[t * 4] = *(const float4*)(h + (size_t)s * 4096 + t * 4);
        *(float4*)&acc[t * 4] = make_float4(0.f, 0.f, 0.f, 0.f);
    }
    if (tid < 64) {
        px[tid] = end_pos[(s * 64 + tid) * 2 + 0];
        py[tid] = end_pos[(s * 64 + tid) * 2 + 1];
        nz[tid] = 0;
    }
    __syncthreads();

    if (tid < 64) {
        float ax = px[i], ay = py[i];
        float tlx = ax - 1.0f, tly = ay + 1.0f;
        float brx = ax + 1.0f, bry = ay - 1.0f;
        float ox = px[tid], oy = py[tid];
        bool oob = (ox >= brx) || (ox <= tlx) || (oy >= tly) || (oy <= bry) || (tid == i);
        int c = -1;
        if (!oob) {
            float cx = floorf((ox - tlx) / 2.0f * 8.0f);
            float cy = floorf((tly - oy) / 2.0f * 8.0f);
            c = (int)(cx + cy * 8.0f);
        }
        cellj[tid] = c;
    }
    __syncthreads();

    for (int j = g * 16; j < g * 16 + 16; j++) {
        int c = cellj[j];
        if (c >= 0) {
            atomicAdd(&acc[c * 64 + d], hsh[j * 64 + d]);
            if (d == 0) nz[c] = 1;
        }
    }
    __syncthreads();

    if (tid == 0) {
        int n = 0;
        for (int c = 0; c < 64; c++) if (nz[c]) slot_cell[n++] = c;
        int base = atomicAdd(&g_R, n);
        sh_base = base; sh_n = n;
        g_base[b] = base; g_nnz[b] = n;
    }
    __syncthreads();

    int base = sh_base, n = sh_n;
    for (int t = g; t < n; t += 4) {
        int c = slot_cell[t];
        g_encR[(size_t)(base + t) * 64 + d] = acc[c * 64 + d];
        if (d == 0) g_rowb[base + t] = b;
    }
}

// ---------------- pipelined fp32x2 SGEMM (R3 mainloop) ----------------
// C = act(A[M,K]@B[K,N] + bias); 128x128 tile, 256 thr, 2-stage cp.async,
// 8x8 micro, FFMA2 with f2rep-built A operands.
// EMPTY: also accumulate relu(C + benc).wfull per row into empty_out.
template<int RELU, int EMPTY>
__global__ void __launch_bounds__(256) k_sgemm(const float* __restrict__ A,
                                               const float* __restrict__ B,
                                               const float* __restrict__ bias,
                                               float* __restrict__ C,
                                               int N, int K,
                                               const float* __restrict__ benc,
                                               const float* __restrict__ wfull,
                                               float* __restrict__ empty_out) {
    __shared__ __align__(16) float As[2][128][16];
    __shared__ __align__(16) float Bs[2][16][128];
    int tid = threadIdx.x;
    int m0 = blockIdx.y * 128;
    int n0 = blockIdx.x * 128;
    int tr = tid >> 4, tc = tid & 15;
    int KT = K >> 4;

    auto stage_load = [&](int st, int k0) {
#pragma unroll
        for (int q = 0; q < 2; q++) {
            int c = tid + q * 256;           // 0..511
            int ar = c >> 2, ak = (c & 3) * 4;
            cpasync16(&As[st][ar][ak], A + (size_t)(m0 + ar) * K + k0 + ak);
            int bk = c >> 5, bc = (c & 31) * 4;
            cpasync16(&Bs[st][bk][bc], B + (size_t)(k0 + bk) * N + n0 + bc);
        }
    };

    ull acc[8][4];
#pragma unroll
    for (int i = 0; i < 8; i++)
#pragma unroll
        for (int j = 0; j < 4; j++) acc[i][j] = 0ull;

    stage_load(0, 0);
    cp_commit();

    for (int it = 0; it < KT; it++) {
        int cur = it & 1;
        cp_wait0();
        __syncthreads();
        if (it + 1 < KT) stage_load(cur ^ 1, (it + 1) * 16);
        cp_commit();

#pragma unroll
        for (int kg = 0; kg < 4; kg++) {
            float4 ar[8];
#pragma unroll
            for (int i = 0; i < 4; i++) {
                ar[i]     = *(float4*)&As[cur][tr * 4 + i][kg * 4];
                ar[4 + i] = *(float4*)&As[cur][64 + tr * 4 + i][kg * 4];
            }
#pragma unroll
            for (int kk = 0; kk < 4; kk++) {
                int k = kg * 4 + kk;
                ulonglong2 b0 = *(ulonglong2*)&Bs[cur][k][tc * 4];
                ulonglong2 b1 = *(ulonglong2*)&Bs[cur][k][64 + tc * 4];
#pragma unroll
                for (int i = 0; i < 8; i++) {
                    ull ap = f2rep(((const float*)&ar[i])[kk]);
                    ffma2(acc[i][0], ap, b0.x); ffma2(acc[i][1], ap, b0.y);
                    ffma2(acc[i][2], ap, b1.x); ffma2(acc[i][3], ap, b1.y);
                }
            }
        }
        __syncthreads();
    }

    float4 bv0 = *(const float4*)(bias + n0 + tc * 4);
    float4 bv1 = *(const float4*)(bias + n0 + 64 + tc * 4);
    float4 be0 = make_float4(0.f, 0.f, 0.f, 0.f), be1 = be0, wf0 = be0, wf1 = be0;
    if (EMPTY) {
        be0 = *(const float4*)(benc + n0 + tc * 4);
        be1 = *(const float4*)(benc + n0 + 64 + tc * 4);
        wf0 = *(const float4*)(wfull + n0 + tc * 4);
        wf1 = *(const float4*)(wfull + n0 + 64 + tc * 4);
    }
#pragma unroll
    for (int i = 0; i < 8; i++) {
        int m = m0 + ((i < 4) ? (tr * 4 + i) : (64 + tr * 4 + i - 4));
        float2 p0 = f2unpack(acc[i][0]);
        float2 p1 = f2unpack(acc[i][1]);
        float2 p2 = f2unpack(acc[i][2]);
        float2 p3 = f2unpack(acc[i][3]);
        float4 o0 = make_float4(p0.x + bv0.x, p0.y + bv0.y, p1.x + bv0.z, p1.y + bv0.w);
        float4 o1 = make_float4(p2.x + bv1.x, p2.y + bv1.y, p3.x + bv1.z, p3.y + bv1.w);
        if (RELU) {
            o0.x = fmaxf(o0.x, 0.f); o0.y = fmaxf(o0.y, 0.f); o0.z = fmaxf(o0.z, 0.f); o0.w = fmaxf(o0.w, 0.f);
            o1.x = fmaxf(o1.x, 0.f); o1.y = fmaxf(o1.y, 0.f); o1.z = fmaxf(o1.z, 0.f); o1.w = fmaxf(o1.w, 0.f);
        }
        *(float4*)(C + (size_t)m * N + n0 + tc * 4)      = o0;
        *(float4*)(C + (size_t)m * N + n0 + 64 + tc * 4) = o1;
        if (EMPTY) {
            float r = 0.f, v;
            v = o0.x + be0.x; if (v > 0.f) r += v * wf0.x;
            v = o0.y + be0.y; if (v > 0.f) r += v * wf0.y;
            v = o0.z + be0.z; if (v > 0.f) r += v * wf0.z;
            v = o0.w + be0.w; if (v > 0.f) r += v * wf0.w;
            v = o1.x + be1.x; if (v > 0.f) r += v * wf1.x;
            v = o1.y + be1.y; if (v > 0.f) r += v * wf1.y;
            v = o1.z + be1.z; if (v > 0.f) r += v * wf1.z;
            v = o1.w + be1.w; if (v > 0.f) r += v * wf1.w;
            r += __shfl_xor_sync(0xffffffffu, r, 1);
            r += __shfl_xor_sync(0xffffffffu, r, 2);
            r += __shfl_xor_sync(0xffffffffu, r, 4);
            r += __shfl_xor_sync(0xffffffffu, r, 8);
            if (tc == 0) atomicAdd(&empty_out[m], r);
        }
    }
}

// ---------------- fused sparse score GEMM (R3 mainloop, lean smem) -----------
// score[r] = sum_a relu(enc_r . Wenc[:,a] + benc[a] + dec[rowb[r],a]) * wfull[a] + bfull
__global__ void __launch_bounds__(256) k_scores(const float* __restrict__ Wenc,
                                                const float* __restrict__ benc,
                                                const float* __restrict__ wfull,
                                                const float* __restrict__ bfull) {
    int R = g_R;
    int r0 = blockIdx.x * 64;
    if (r0 >= R) return;

    __shared__ __align__(16) float As[64][68];   // [k][row]
    __shared__ __align__(16) float Bs[2][16][128];

    int tid = threadIdx.x;  // 256
    int tr = tid >> 4, tc = tid & 15;
    float bf0 = bfull[0];

    // A tile load + transpose (64 rows x 64 k), zero-pad rows >= R
#pragma unroll
    for (int it = 0; it < 4; it++) {
        int t = tid + it * 256;
        int row = t >> 4;
        int kq = (t & 15) * 4;
        float4 v = make_float4(0.f, 0.f, 0.f, 0.f);
        if (r0 + row < R) v = *(const float4*)(g_encR + (size_t)(r0 + row) * 64 + kq);
        As[kq + 0][row] = v.x; As[kq + 1][row] = v.y;
        As[kq + 2][row] = v.z; As[kq + 3][row] = v.w;
    }
    int brow[4];
#pragma unroll
    for (int i = 0; i < 4; i++) {
        int rr = r0 + tr * 4 + i;
        brow[i] = (rr < R) ? g_rowb[rr] : 0;
    }

    auto stage_load = [&](int st, int t) {
        int ks = t & 3, ct = t >> 2;
#pragma unroll
        for (int q = 0; q < 2; q++) {
            int c = tid + q * 256;
            int kr = c >> 5, cc = (c & 31) * 4;
            cpasync16(&Bs[st][kr][cc], Wenc + (size_t)(ks * 16 + kr) * 1024 + ct * 128 + cc);
        }
    };

    float rowsum[4] = {0.f, 0.f, 0.f, 0.f};
    ull acc[4][4];

    stage_load(0, 0);
    cp_commit();

    for (int t = 0; t < 32; t++) {
        int cur = t & 1;
        int ks = t & 3, ct = t >> 2;
        cp_wait0();
        __syncthreads();
        if (t + 1 < 32) stage_load(cur ^ 1, t + 1);
        cp_commit();

        if (ks == 0) {
#pragma unroll
            for (int i = 0; i < 4; i++)
#pragma unroll
                for (int j = 0; j < 4; j++) acc[i][j] = 0ull;
        }

#pragma unroll
        for (int k = 0; k < 16; k++) {
            int kk = ks * 16 + k;
            float4 a = *(float4*)&As[kk][tr * 4];
            ulonglong2 b0 = *(ulonglong2*)&Bs[cur][k][tc * 4];
            ulonglong2 b1 = *(ulonglong2*)&Bs[cur][k][64 + tc * 4];
            ull ap;
            ap = f2rep(a.x); ffma2(acc[0][0], ap, b0.x); ffma2(acc[0][1], ap, b0.y); ffma2(acc[0][2], ap, b1.x); ffma2(acc[0][3], ap, b1.y);
            ap = f2rep(a.y); ffma2(acc[1][0], ap, b0.x); ffma2(acc[1][1], ap, b0.y); ffma2(acc[1][2], ap, b1.x); ffma2(acc[1][3], ap, b1.y);
            ap = f2rep(a.z); ffma2(acc[2][0], ap, b0.x); ffma2(acc[2][1], ap, b0.y); ffma2(acc[2][2], ap, b1.x); ffma2(acc[2][3], ap, b1.y);
            ap = f2rep(a.w); ffma2(acc[3][0], ap, b0.x); ffma2(acc[3][1], ap, b0.y); ffma2(acc[3][2], ap, b1.x); ffma2(acc[3][3], ap, b1.y);
        }

        if (ks == 3) {
            int n0 = ct * 128;
            float4 be0 = *(const float4*)(benc + n0 + tc * 4);
            float4 be1 = *(const float4*)(benc + n0 + 64 + tc * 4);
            float4 wf0 = *(const float4*)(wfull + n0 + tc * 4);
            float4 wf1 = *(const float4*)(wfull + n0 + 64 + tc * 4);
#pragma unroll
            for (int i = 0; i < 4; i++) {
                const float* decrow = g_dec + (size_t)brow[i] * 1024 + n0;
                float4 d0 = *(const float4*)(decrow + tc * 4);
                float4 d1 = *(const float4*)(decrow + 64 + tc * 4);
                float2 p0 = f2unpack(acc[i][0]);
                float2 p1 = f2unpack(acc[i][1]);
                float2 p2 = f2unpack(acc[i][2]);
                float2 p3 = f2unpack(acc[i][3]);
                float rs = 0.f, v;
                v = p0.x + be0.x + d0.x; if (v > 0.f) rs += v * wf0.x;
                v = p0.y + be0.y + d0.y; if (v > 0.f) rs += v * wf0.y;
                v = p1.x + be0.z + d0.z; if (v > 0.f) rs += v * wf0.z;
                v = p1.y + be0.w + d0.w; if (v > 0.f) rs += v * wf0.w;
                v = p2.x + be1.x + d1.x; if (v > 0.f) rs += v * wf1.x;
                v = p2.y + be1.y + d1.y; if (v > 0.f) rs += v * wf1.y;
                v = p3.x + be1.z + d1.z; if (v > 0.f) rs += v * wf1.z;
                v = p3.y + be1.w + d1.w; if (v > 0.f) rs += v * wf1.w;
                rowsum[i] += rs;
            }
        }
    }

#pragma unroll
    for (int i = 0; i < 4; i++) {
        float r = rowsum[i];
        r += __shfl_xor_sync(0xffffffffu, r, 1);
        r += __shfl_xor_sync(0xffffffffu, r, 2);
        r += __shfl_xor_sync(0xffffffffu, r, 4);
        r += __shfl_xor_sync(0xffffffffu, r, 8);
        int rr = r0 + tr * 4 + i;
        if (tc == 0 && rr < R) g_scoreR[rr] = r + bf0;
    }
}

// ---------------- softmax + ctx + embed (64 thr/anchor) ----------------
__global__ void k_softctx(const float* __restrict__ bfull, const float* __restrict__ end_pos,
                          const float* __restrict__ rel_pos, const float* __restrict__ Wemb,
                          const float* __restrict__ bemb) {
    int b = blockIdx.x;
    int tid = threadIdx.x;  // 64
    __shared__ float sc[64];
    __shared__ float alpha[64];

    int base = g_base[b], nnz = g_nnz[b];
    if (tid < nnz) sc[tid] = g_scoreR[base + tid];
    __syncthreads();
    if (tid == 0) {
        float se = g_empty[b] + bfull[0];
        float m = se;
        for (int t = 0; t < nnz; t++) m = fmaxf(m, sc[t]);
        float Z = (float)(64 - nnz) * expf(se - m);
        for (int t = 0; t < nnz; t++) { float e = expf(sc[t] - m); alpha[t] = e; Z += e; }
        float inv = 1.0f / Z;
        for (int t = 0; t < nnz; t++) alpha[t] *= inv;
    }
    __syncthreads();

    float c = 0.f;
    for (int t = 0; t < nnz; t++) c += alpha[t] * g_encR[(size_t)(base + t) * 64 + tid];
    g_ctxemb[b * PADK + tid] = c;

    if (tid < 4) {
        float v = end_pos[b * 2 + 0] * Wemb[0 * 4 + tid] + end_pos[b * 2 + 1] * Wemb[1 * 4 + tid]
                + rel_pos[b * 2 + 0] * Wemb[2 * 4 + tid] + rel_pos[b * 2 + 1] * Wemb[3 * 4 + tid]
                + bemb[tid];
        g_ctxemb[b * PADK + 64 + tid] = v > 0.f ? v : 0.f;
    } else if (tid < 16) {
        g_ctxemb[b * PADK + 64 + tid] = 0.f;
    }
}

// ---------------- batchnorm: partial sums + final + apply --------
__global__ void k_bnpart() {
    int bc = blockIdx.x & 15;
    int rs = blockIdx.x >> 4;
    int c = bc * 64 + (threadIdx.x & 63);
    int rg = threadIdx.x >> 6;
    float s = 0.f, s2 = 0.f;
    for (int r = rs * 256 + rg; r < (rs + 1) * 256; r += 4) {
        float v = g_x[(size_t)r * ATTD + c];
        s += v; s2 += v * v;
    }
    __shared__ float ss[4][64], ss2[4][64];
    ss[rg][threadIdx.x & 63] = s; ss2[rg][threadIdx.x & 63] = s2;
    __syncthreads();
    if (rg == 0) {
        int l = threadIdx.x & 63;
        float t  = ss[0][l] + ss[1][l] + ss[2][l] + ss[3][l];
        float t2 = ss2[0][l] + ss2[1][l] + ss2[2][l] + ss2[3][l];
        atomicAdd(&g_bnsum[c], t);
        atomicAdd(&g_bnsum2[c], t2);
    }
}

__global__ void k_bnfinal(const float* __restrict__ gamma, const float* __restrict__ beta) {
    int c = threadIdx.x;
    float mu = g_bnsum[c] / (float)BQ;
    float var = g_bnsum2[c] / (float)BQ - mu * mu;
    float rstd = rsqrtf(var + 1e-5f);
    float ga = gamma[c] * rstd;
    g_bna[c] = ga;
    g_bnb[c] = beta[c] - mu * ga;
}

__global__ void k_bnapply(float* __restrict__ out) {
    int idx = blockIdx.x * blockDim.x + threadIdx.x;
    if (idx < BQ * ATTD) {
        int c = idx & 1023;
        float v = g_x[idx] * g_bna[c] + g_bnb[c];
        out[idx] = v > 0.f ? v : 0.f;
    }
}

// ---------------- launch ----------------
extern "C" void kernel_launch(void* const* d_in, const int* in_sizes, int n_in,
                              void* d_out, int out_size) {
    const float* h       = (const float*)d_in[0];
    const float* end_pos = (const float*)d_in[2];
    const float* rel_pos = (const float*)d_in[3];
    const float* Wenc    = (const float*)d_in[4];
    const float* benc    = (const float*)d_in[5];
    const float* Wdec    = (const float*)d_in[6];
    const float* bdec    = (const float*)d_in[7];
    const float* wfull   = (const float*)d_in[8];
    const float* bfull   = (const float*)d_in[9];
    const float* Wemb    = (const float*)d_in[10];
    const float* bemb    = (const float*)d_in[11];
    const float* Wout    = (const float*)d_in[12];
    const float* bout    = (const float*)d_in[13];
    const float* Wmlp    = (const float*)d_in[14];
    const float* bmlp    = (const float*)d_in[15];
    const float* gamma   = (const float*)d_in[16];
    const float* beta    = (const float*)d_in[17];
    float* out = (float*)d_out;

    float *p_dec, *p_ctxemb, *p_WoutP, *p_out, *p_x, *p_empty;
    cudaGetSymbolAddress((void**)&p_dec,    g_dec);
    cudaGetSymbolAddress((void**)&p_ctxemb, g_ctxemb);
    cudaGetSymbolAddress((void**)&p_WoutP,  g_WoutP);
    cudaGetSymbolAddress((void**)&p_out,    g_out);
    cudaGetSymbolAddress((void**)&p_x,      g_x);
    cudaGetSymbolAddress((void**)&p_empty,  g_empty);

    dim3 gg(ATTD / 128, BQ / 128);   // (8, 16) = 128 blocks

    k_prep<<<(PADK * ATTD + 255) / 256, 256>>>(Wout);
    k_pool<<<BQ, 256>>>(h, end_pos);
    k_sgemm<0, 1><<<gg, 256>>>(h, Wdec, bdec, p_dec, ATTD, HD, benc, wfull, p_empty);
    k_scores<<<BQ, 256>>>(Wenc, benc, wfull, bfull);
    k_softctx<<<BQ, 64>>>(bfull, end_pos, rel_pos, Wemb, bemb);
    k_sgemm<1, 0><<<gg, 256>>>(p_ctxemb, p_WoutP, bout, p_out, ATTD, PADK, nullptr, nullptr, nullptr);
    k_sgemm<0, 0><<<gg, 256>>>(p_out, Wmlp, bmlp, p_x, ATTD, ATTD, nullptr, nullptr, nullptr);
    k_bnpart<<<128, 256>>>();
    k_bnfinal<<<1, 1024>>>(gamma, beta);
    k_bnapply<<<(BQ * ATTD + 255) / 256, 256>>>(out);
}

// round 6
// speedup vs baseline: 1.0920x; 1.0045x over previous
#include <cuda_runtime.h>
#include <math.h>

#define BQ   2048     // total agents (B)
#define HD   64
#define ATTD 1024
#define PADK 80       // 68 padded to multiple of 16

typedef unsigned long long ull;

// ---------------- packed f32x2 helpers ----------------
__device__ __forceinline__ void ffma2(ull& d, ull a, ull b) {
    asm("fma.rn.f32x2 %0, %1, %2, %0;" : "+l"(d) : "l"(a), "l"(b));
}
__device__ __forceinline__ ull f2rep(float x) {
    ull r; asm("mov.b64 %0, {%1, %1};" : "=l"(r) : "f"(x)); return r;
}
__device__ __forceinline__ float2 f2unpack(ull v) {
    float2 r; asm("mov.b64 {%0, %1}, %2;" : "=f"(r.x), "=f"(r.y) : "l"(v)); return r;
}
// ---------------- cp.async helpers ----------------
__device__ __forceinline__ void cpasync16(void* smem, const void* g) {
    unsigned sa = (unsigned)__cvta_generic_to_shared(smem);
    asm volatile("cp.async.cg.shared.global [%0], [%1], 16;" :: "r"(sa), "l"(g));
}
__device__ __forceinline__ void cp_commit() { asm volatile("cp.async.commit_group;"); }
__device__ __forceinline__ void cp_wait0()  { asm volatile("cp.async.wait_group 0;"); }

// ---------------- device scratch ----------------
__device__ float g_dec[BQ * ATTD];
__device__ float g_encR[(size_t)BQ * 64 * HD];
__device__ int   g_rowb[BQ * 64];
__device__ int   g_base[BQ];
__device__ int   g_nnz[BQ];
__device__ float g_scoreR[BQ * 64];
__device__ int   g_R;
__device__ float g_empty[BQ];
__device__ float g_ctxemb[BQ * PADK];
__device__ float g_WoutP[PADK * ATTD];
__device__ float g_out[BQ * ATTD];
__device__ float g_x[BQ * ATTD];
__device__ float g_bnsum[ATTD];
__device__ float g_bnsum2[ATTD];
__device__ float g_bna[ATTD];
__device__ float g_bnb[ATTD];

// ---------------- prep: pad W_out + zero counters ----------------
__global__ void k_prep(const float* __restrict__ Wout) {
    int idx = blockIdx.x * blockDim.x + threadIdx.x;
    if (idx < PADK * ATTD) g_WoutP[idx] = ((idx >> 10) < 68) ? Wout[idx] : 0.f;
    if (idx < ATTD) { g_bnsum[idx] = 0.f; g_bnsum2[idx] = 0.f; }
    if (idx < BQ) g_empty[idx] = 0.f;
    if (idx == 0) g_R = 0;
}

// ---------------- social pooling + compaction (256 thr/anchor) ----------------
__global__ void k_pool(const float* __restrict__ h, const float* __restrict__ end_pos) {
    int b = blockIdx.x;
    int s = b >> 6;
    int i = b & 63;
    int tid = threadIdx.x;      // 256
    int d = tid & 63;
    int g = tid >> 6;

    __shared__ __align__(16) float hsh[4096];
    __shared__ __align__(16) float acc[4096];
    __shared__ float px[64], py[64];
    __shared__ int   cellj[64];
    __shared__ int   nz[64];
    __shared__ int   slot_cell[64];
    __shared__ int   sh_base, sh_n;

    for (int t = tid; t < 1024; t += 256) {
        *(float4*)&hsh[t * 4] = *(const float4*)(h + (size_t)s * 4096 + t * 4);
        *(float4*)&acc[t * 4] = make_float4(0.f, 0.f, 0.f, 0.f);
    }
    if (tid < 64) {
        px[tid] = end_pos[(s * 64 + tid) * 2 + 0];
        py[tid] = end_pos[(s * 64 + tid) * 2 + 1];
        nz[tid] = 0;
    }
    __syncthreads();

    if (tid < 64) {
        float ax = px[i], ay = py[i];
        float tlx = ax - 1.0f, tly = ay + 1.0f;
        float brx = ax + 1.0f, bry = ay - 1.0f;
        float ox = px[tid], oy = py[tid];
        bool oob = (ox >= brx) || (ox <= tlx) || (oy >= tly) || (oy <= bry) || (tid == i);
        int c = -1;
        if (!oob) {
            float cx = floorf((ox - tlx) / 2.0f * 8.0f);
            float cy = floorf((tly - oy) / 2.0f * 8.0f);
            c = (int)(cx + cy * 8.0f);
        }
        cellj[tid] = c;
    }
    __syncthreads();

    for (int j = g * 16; j < g * 16 + 16; j++) {
        int c = cellj[j];
        if (c >= 0) {
            atomicAdd(&acc[c * 64 + d], hsh[j * 64 + d]);
            if (d == 0) nz[c] = 1;
        }
    }
    __syncthreads();

    if (tid == 0) {
        int n = 0;
        for (int c = 0; c < 64; c++) if (nz[c]) slot_cell[n++] = c;
        int base = atomicAdd(&g_R, n);
        sh_base = base; sh_n = n;
        g_base[b] = base; g_nnz[b] = n;
    }
    __syncthreads();

    int base = sh_base, n = sh_n;
    for (int t = g; t < n; t += 4) {
        int c = slot_cell[t];
        g_encR[(size_t)(base + t) * 64 + d] = acc[c * 64 + d];
        if (d == 0) g_rowb[base + t] = b;
    }
}

// ---------------- pipelined fp32x2 SGEMM (R3 mainloop) ----------------
// C = act(A[M,K]@B[K,N] + bias); 128x128 tile, 256 thr, 2-stage cp.async,
// 8x8 micro, FFMA2 with f2rep-built A operands.
// EMPTY: also accumulate relu(C + benc).wfull per row into empty_out.
template<int RELU, int EMPTY>
__global__ void __launch_bounds__(256) k_sgemm(const float* __restrict__ A,
                                               const float* __restrict__ B,
                                               const float* __restrict__ bias,
                                               float* __restrict__ C,
                                               int N, int K,
                                               const float* __restrict__ benc,
                                               const float* __restrict__ wfull,
                                               float* __restrict__ empty_out) {
    __shared__ __align__(16) float As[2][128][16];
    __shared__ __align__(16) float Bs[2][16][128];
    int tid = threadIdx.x;
    int m0 = blockIdx.y * 128;
    int n0 = blockIdx.x * 128;
    int tr = tid >> 4, tc = tid & 15;
    int KT = K >> 4;

    auto stage_load = [&](int st, int k0) {
#pragma unroll
        for (int q = 0; q < 2; q++) {
            int c = tid + q * 256;           // 0..511
            int ar = c >> 2, ak = (c & 3) * 4;
            cpasync16(&As[st][ar][ak], A + (size_t)(m0 + ar) * K + k0 + ak);
            int bk = c >> 5, bc = (c & 31) * 4;
            cpasync16(&Bs[st][bk][bc], B + (size_t)(k0 + bk) * N + n0 + bc);
        }
    };

    ull acc[8][4];
#pragma unroll
    for (int i = 0; i < 8; i++)
#pragma unroll
        for (int j = 0; j < 4; j++) acc[i][j] = 0ull;

    stage_load(0, 0);
    cp_commit();

    for (int it = 0; it < KT; it++) {
        int cur = it & 1;
        cp_wait0();
        __syncthreads();
        if (it + 1 < KT) stage_load(cur ^ 1, (it + 1) * 16);
        cp_commit();

#pragma unroll
        for (int kg = 0; kg < 4; kg++) {
            float4 ar[8];
#pragma unroll
            for (int i = 0; i < 4; i++) {
                ar[i]     = *(float4*)&As[cur][tr * 4 + i][kg * 4];
                ar[4 + i] = *(float4*)&As[cur][64 + tr * 4 + i][kg * 4];
            }
#pragma unroll
            for (int kk = 0; kk < 4; kk++) {
                int k = kg * 4 + kk;
                ulonglong2 b0 = *(ulonglong2*)&Bs[cur][k][tc * 4];
                ulonglong2 b1 = *(ulonglong2*)&Bs[cur][k][64 + tc * 4];
#pragma unroll
                for (int i = 0; i < 8; i++) {
                    ull ap = f2rep(((const float*)&ar[i])[kk]);
                    ffma2(acc[i][0], ap, b0.x); ffma2(acc[i][1], ap, b0.y);
                    ffma2(acc[i][2], ap, b1.x); ffma2(acc[i][3], ap, b1.y);
                }
            }
        }
        __syncthreads();
    }

    float4 bv0 = *(const float4*)(bias + n0 + tc * 4);
    float4 bv1 = *(const float4*)(bias + n0 + 64 + tc * 4);
    float4 be0 = make_float4(0.f, 0.f, 0.f, 0.f), be1 = be0, wf0 = be0, wf1 = be0;
    if (EMPTY) {
        be0 = *(const float4*)(benc + n0 + tc * 4);
        be1 = *(const float4*)(benc + n0 + 64 + tc * 4);
        wf0 = *(const float4*)(wfull + n0 + tc * 4);
        wf1 = *(const float4*)(wfull + n0 + 64 + tc * 4);
    }
#pragma unroll
    for (int i = 0; i < 8; i++) {
        int m = m0 + ((i < 4) ? (tr * 4 + i) : (64 + tr * 4 + i - 4));
        float2 p0 = f2unpack(acc[i][0]);
        float2 p1 = f2unpack(acc[i][1]);
        float2 p2 = f2unpack(acc[i][2]);
        float2 p3 = f2unpack(acc[i][3]);
        float4 o0 = make_float4(p0.x + bv0.x, p0.y + bv0.y, p1.x + bv0.z, p1.y + bv0.w);
        float4 o1 = make_float4(p2.x + bv1.x, p2.y + bv1.y, p3.x + bv1.z, p3.y + bv1.w);
        if (RELU) {
            o0.x = fmaxf(o0.x, 0.f); o0.y = fmaxf(o0.y, 0.f); o0.z = fmaxf(o0.z, 0.f); o0.w = fmaxf(o0.w, 0.f);
            o1.x = fmaxf(o1.x, 0.f); o1.y = fmaxf(o1.y, 0.f); o1.z = fmaxf(o1.z, 0.f); o1.w = fmaxf(o1.w, 0.f);
        }
        *(float4*)(C + (size_t)m * N + n0 + tc * 4)      = o0;
        *(float4*)(C + (size_t)m * N + n0 + 64 + tc * 4) = o1;
        if (EMPTY) {
            float r = 0.f, v;
            v = o0.x + be0.x; if (v > 0.f) r += v * wf0.x;
            v = o0.y + be0.y; if (v > 0.f) r += v * wf0.y;
            v = o0.z + be0.z; if (v > 0.f) r += v * wf0.z;
            v = o0.w + be0.w; if (v > 0.f) r += v * wf0.w;
            v = o1.x + be1.x; if (v > 0.f) r += v * wf1.x;
            v = o1.y + be1.y; if (v > 0.f) r += v * wf1.y;
            v = o1.z + be1.z; if (v > 0.f) r += v * wf1.z;
            v = o1.w + be1.w; if (v > 0.f) r += v * wf1.w;
            r += __shfl_xor_sync(0xffffffffu, r, 1);
            r += __shfl_xor_sync(0xffffffffu, r, 2);
            r += __shfl_xor_sync(0xffffffffu, r, 4);
            r += __shfl_xor_sync(0xffffffffu, r, 8);
            if (tc == 0) atomicAdd(&empty_out[m], r);
        }
    }
}

// ---------------- fused sparse score GEMM: 128-row tile, 8x8 micro -----------
// score[r] = sum_a relu(enc_r . Wenc[:,a] + benc[a] + dec[rowb[r],a]) * wfull[a] + bfull
__global__ void __launch_bounds__(256) k_scores(const float* __restrict__ Wenc,
                                                const float* __restrict__ benc,
                                                const float* __restrict__ wfull,
                                                const float* __restrict__ bfull) {
    int R = g_R;
    int r0 = blockIdx.x * 128;
    if (r0 >= R) return;

    __shared__ __align__(16) float As[64][128];   // [k][row] : 32 KB
    __shared__ __align__(16) float Bs[2][16][128];//           16 KB  (total 48 KB)

    int tid = threadIdx.x;  // 256
    int tr = tid >> 4, tc = tid & 15;
    float bf0 = bfull[0];

    // A tile fill: 128 rows x 64 k. row-fastest mapping -> conflict-free STS.
#pragma unroll
    for (int it = 0; it < 8; it++) {
        int c = tid + it * 256;       // 0..2047
        int row = c & 127;
        int kq = (c >> 7) * 4;
        float4 v = make_float4(0.f, 0.f, 0.f, 0.f);
        if (r0 + row < R) v = *(const float4*)(g_encR + (size_t)(r0 + row) * 64 + kq);
        As[kq + 0][row] = v.x; As[kq + 1][row] = v.y;
        As[kq + 2][row] = v.z; As[kq + 3][row] = v.w;
    }
    int brow[8];
#pragma unroll
    for (int i = 0; i < 8; i++) {
        int rr = r0 + ((i < 4) ? (tr * 4 + i) : (64 + tr * 4 + i - 4));
        brow[i] = (rr < R) ? g_rowb[rr] : 0;
    }

    auto stage_load = [&](int st, int t) {
        int ks = t & 3, ct = t >> 2;
#pragma unroll
        for (int q = 0; q < 2; q++) {
            int c = tid + q * 256;
            int kr = c >> 5, cc = (c & 31) * 4;
            cpasync16(&Bs[st][kr][cc], Wenc + (size_t)(ks * 16 + kr) * 1024 + ct * 128 + cc);
        }
    };

    float rowsum[8] = {0.f, 0.f, 0.f, 0.f, 0.f, 0.f, 0.f, 0.f};
    ull acc[8][4];

    stage_load(0, 0);
    cp_commit();

    for (int t = 0; t < 32; t++) {
        int cur = t & 1;
        int ks = t & 3, ct = t >> 2;
        cp_wait0();
        __syncthreads();
        if (t + 1 < 32) stage_load(cur ^ 1, t + 1);
        cp_commit();

        if (ks == 0) {
#pragma unroll
            for (int i = 0; i < 8; i++)
#pragma unroll
                for (int j = 0; j < 4; j++) acc[i][j] = 0ull;
        }

#pragma unroll
        for (int k = 0; k < 16; k++) {
            int kk = ks * 16 + k;
            float4 a0 = *(float4*)&As[kk][tr * 4];
            float4 a1 = *(float4*)&As[kk][64 + tr * 4];
            ulonglong2 b0 = *(ulonglong2*)&Bs[cur][k][tc * 4];
            ulonglong2 b1 = *(ulonglong2*)&Bs[cur][k][64 + tc * 4];
            ull ap;
            ap = f2rep(a0.x); ffma2(acc[0][0], ap, b0.x); ffma2(acc[0][1], ap, b0.y); ffma2(acc[0][2], ap, b1.x); ffma2(acc[0][3], ap, b1.y);
            ap = f2rep(a0.y); ffma2(acc[1][0], ap, b0.x); ffma2(acc[1][1], ap, b0.y); ffma2(acc[1][2], ap, b1.x); ffma2(acc[1][3], ap, b1.y);
            ap = f2rep(a0.z); ffma2(acc[2][0], ap, b0.x); ffma2(acc[2][1], ap, b0.y); ffma2(acc[2][2], ap, b1.x); ffma2(acc[2][3], ap, b1.y);
            ap = f2rep(a0.w); ffma2(acc[3][0], ap, b0.x); ffma2(acc[3][1], ap, b0.y); ffma2(acc[3][2], ap, b1.x); ffma2(acc[3][3], ap, b1.y);
            ap = f2rep(a1.x); ffma2(acc[4][0], ap, b0.x); ffma2(acc[4][1], ap, b0.y); ffma2(acc[4][2], ap, b1.x); ffma2(acc[4][3], ap, b1.y);
            ap = f2rep(a1.y); ffma2(acc[5][0], ap, b0.x); ffma2(acc[5][1], ap, b0.y); ffma2(acc[5][2], ap, b1.x); ffma2(acc[5][3], ap, b1.y);
            ap = f2rep(a1.z); ffma2(acc[6][0], ap, b0.x); ffma2(acc[6][1], ap, b0.y); ffma2(acc[6][2], ap, b1.x); ffma2(acc[6][3], ap, b1.y);
            ap = f2rep(a1.w); ffma2(acc[7][0], ap, b0.x); ffma2(acc[7][1], ap, b0.y); ffma2(acc[7][2], ap, b1.x); ffma2(acc[7][3], ap, b1.y);
        }

        if (ks == 3) {
            int n0 = ct * 128;
            float4 be0 = *(const float4*)(benc + n0 + tc * 4);
            float4 be1 = *(const float4*)(benc + n0 + 64 + tc * 4);
            float4 wf0 = *(const float4*)(wfull + n0 + tc * 4);
            float4 wf1 = *(const float4*)(wfull + n0 + 64 + tc * 4);
#pragma unroll
            for (int i = 0; i < 8; i++) {
                const float* decrow = g_dec + (size_t)brow[i] * 1024 + n0;
                float4 d0 = *(const float4*)(decrow + tc * 4);
                float4 d1 = *(const float4*)(decrow + 64 + tc * 4);
                float2 p0 = f2unpack(acc[i][0]);
                float2 p1 = f2unpack(acc[i][1]);
                float2 p2 = f2unpack(acc[i][2]);
                float2 p3 = f2unpack(acc[i][3]);
                float rs = 0.f, v;
                v = p0.x + be0.x + d0.x; if (v > 0.f) rs += v * wf0.x;
                v = p0.y + be0.y + d0.y; if (v > 0.f) rs += v * wf0.y;
                v = p1.x + be0.z + d0.z; if (v > 0.f) rs += v * wf0.z;
                v = p1.y + be0.w + d0.w; if (v > 0.f) rs += v * wf0.w;
                v = p2.x + be1.x + d1.x; if (v > 0.f) rs += v * wf1.x;
                v = p2.y + be1.y + d1.y; if (v > 0.f) rs += v * wf1.y;
                v = p3.x + be1.z + d1.z; if (v > 0.f) rs += v * wf1.z;
                v = p3.y + be1.w + d1.w; if (v > 0.f) rs += v * wf1.w;
                rowsum[i] += rs;
            }
        }
    }

#pragma unroll
    for (int i = 0; i < 8; i++) {
        float r = rowsum[i];
        r += __shfl_xor_sync(0xffffffffu, r, 1);
        r += __shfl_xor_sync(0xffffffffu, r, 2);
        r += __shfl_xor_sync(0xffffffffu, r, 4);
        r += __shfl_xor_sync(0xffffffffu, r, 8);
        int rr = r0 + ((i < 4) ? (tr * 4 + i) : (64 + tr * 4 + i - 4));
        if (tc == 0 && rr < R) g_scoreR[rr] = r + bf0;
    }
}

// ---------------- softmax + ctx + embed (64 thr/anchor) ----------------
__global__ void k_softctx(const float* __restrict__ bfull, const float* __restrict__ end_pos,
                          const float* __restrict__ rel_pos, const float* __restrict__ Wemb,
                          const float* __restrict__ bemb) {
    int b = blockIdx.x;
    int tid = threadIdx.x;  // 64
    __shared__ float sc[64];
    __shared__ float alpha[64];

    int base = g_base[b], nnz = g_nnz[b];
    if (tid < nnz) sc[tid] = g_scoreR[base + tid];
    __syncthreads();
    if (tid == 0) {
        float se = g_empty[b] + bfull[0];
        float m = se;
        for (int t = 0; t < nnz; t++) m = fmaxf(m, sc[t]);
        float Z = (float)(64 - nnz) * expf(se - m);
        for (int t = 0; t < nnz; t++) { float e = expf(sc[t] - m); alpha[t] = e; Z += e; }
        float inv = 1.0f / Z;
        for (int t = 0; t < nnz; t++) alpha[t] *= inv;
    }
    __syncthreads();

    float c = 0.f;
    for (int t = 0; t < nnz; t++) c += alpha[t] * g_encR[(size_t)(base + t) * 64 + tid];
    g_ctxemb[b * PADK + tid] = c;

    if (tid < 4) {
        float v = end_pos[b * 2 + 0] * Wemb[0 * 4 + tid] + end_pos[b * 2 + 1] * Wemb[1 * 4 + tid]
                + rel_pos[b * 2 + 0] * Wemb[2 * 4 + tid] + rel_pos[b * 2 + 1] * Wemb[3 * 4 + tid]
                + bemb[tid];
        g_ctxemb[b * PADK + 64 + tid] = v > 0.f ? v : 0.f;
    } else if (tid < 16) {
        g_ctxemb[b * PADK + 64 + tid] = 0.f;
    }
}

// ---------------- batchnorm: partial sums + final + apply --------
__global__ void k_bnpart() {
    int bc = blockIdx.x & 15;
    int rs = blockIdx.x >> 4;
    int c = bc * 64 + (threadIdx.x & 63);
    int rg = threadIdx.x >> 6;
    float s = 0.f, s2 = 0.f;
    for (int r = rs * 256 + rg; r < (rs + 1) * 256; r += 4) {
        float v = g_x[(size_t)r * ATTD + c];
        s += v; s2 += v * v;
    }
    __shared__ float ss[4][64], ss2[4][64];
    ss[rg][threadIdx.x & 63] = s; ss2[rg][threadIdx.x & 63] = s2;
    __syncthreads();
    if (rg == 0) {
        int l = threadIdx.x & 63;
        float t  = ss[0][l] + ss[1][l] + ss[2][l] + ss[3][l];
        float t2 = ss2[0][l] + ss2[1][l] + ss2[2][l] + ss2[3][l];
        atomicAdd(&g_bnsum[c], t);
        atomicAdd(&g_bnsum2[c], t2);
    }
}

__global__ void k_bnfinal(const float* __restrict__ gamma, const float* __restrict__ beta) {
    int c = threadIdx.x;
    float mu = g_bnsum[c] / (float)BQ;
    float var = g_bnsum2[c] / (float)BQ - mu * mu;
    float rstd = rsqrtf(var + 1e-5f);
    float ga = gamma[c] * rstd;
    g_bna[c] = ga;
    g_bnb[c] = beta[c] - mu * ga;
}

__global__ void k_bnapply(float* __restrict__ out) {
    int idx = blockIdx.x * blockDim.x + threadIdx.x;
    if (idx < BQ * ATTD) {
        int c = idx & 1023;
        float v = g_x[idx] * g_bna[c] + g_bnb[c];
        out[idx] = v > 0.f ? v : 0.f;
    }
}

// ---------------- launch ----------------
extern "C" void kernel_launch(void* const* d_in, const int* in_sizes, int n_in,
                              void* d_out, int out_size) {
    const float* h       = (const float*)d_in[0];
    const float* end_pos = (const float*)d_in[2];
    const float* rel_pos = (const float*)d_in[3];
    const float* Wenc    = (const float*)d_in[4];
    const float* benc    = (const float*)d_in[5];
    const float* Wdec    = (const float*)d_in[6];
    const float* bdec    = (const float*)d_in[7];
    const float* wfull   = (const float*)d_in[8];
    const float* bfull   = (const float*)d_in[9];
    const float* Wemb    = (const float*)d_in[10];
    const float* bemb    = (const float*)d_in[11];
    const float* Wout    = (const float*)d_in[12];
    const float* bout    = (const float*)d_in[13];
    const float* Wmlp    = (const float*)d_in[14];
    const float* bmlp    = (const float*)d_in[15];
    const float* gamma   = (const float*)d_in[16];
    const float* beta    = (const float*)d_in[17];
    float* out = (float*)d_out;

    float *p_dec, *p_ctxemb, *p_WoutP, *p_out, *p_x, *p_empty;
    cudaGetSymbolAddress((void**)&p_dec,    g_dec);
    cudaGetSymbolAddress((void**)&p_ctxemb, g_ctxemb);
    cudaGetSymbolAddress((void**)&p_WoutP,  g_WoutP);
    cudaGetSymbolAddress((void**)&p_out,    g_out);
    cudaGetSymbolAddress((void**)&p_x,      g_x);
    cudaGetSymbolAddress((void**)&p_empty,  g_empty);

    dim3 gg(ATTD / 128, BQ / 128);   // (8, 16) = 128 blocks

    k_prep<<<(PADK * ATTD + 255) / 256, 256>>>(Wout);
    k_pool<<<BQ, 256>>>(h, end_pos);
    k_sgemm<0, 1><<<gg, 256>>>(h, Wdec, bdec, p_dec, ATTD, HD, benc, wfull, p_empty);
    k_scores<<<BQ * 64 / 128, 256>>>(Wenc, benc, wfull, bfull);
    k_softctx<<<BQ, 64>>>(bfull, end_pos, rel_pos, Wemb, bemb);
    k_sgemm<1, 0><<<gg, 256>>>(p_ctxemb, p_WoutP, bout, p_out, ATTD, PADK, nullptr, nullptr, nullptr);
    k_sgemm<0, 0><<<gg, 256>>>(p_out, Wmlp, bmlp, p_x, ATTD, ATTD, nullptr, nullptr, nullptr);
    k_bnpart<<<128, 256>>>();
    k_bnfinal<<<1, 1024>>>(gamma, beta);
    k_bnapply<<<(BQ * ATTD + 255) / 256, 256>>>(out);
}

// round 7
// speedup vs baseline: 1.1711x; 1.0725x over previous
#include <cuda_runtime.h>
#include <math.h>

#define BQ   2048     // total agents (B)
#define HD   64
#define ATTD 1024
#define PADK 80       // 68 padded to multiple of 16

typedef unsigned long long ull;

// ---------------- packed f32x2 helpers ----------------
__device__ __forceinline__ void ffma2(ull& d, ull a, ull b) {
    asm("fma.rn.f32x2 %0, %1, %2, %0;" : "+l"(d) : "l"(a), "l"(b));
}
__device__ __forceinline__ ull f2rep(float x) {
    ull r; asm("mov.b64 %0, {%1, %1};" : "=l"(r) : "f"(x)); return r;
}
__device__ __forceinline__ float2 f2unpack(ull v) {
    float2 r; asm("mov.b64 {%0, %1}, %2;" : "=f"(r.x), "=f"(r.y) : "l"(v)); return r;
}
// ---------------- cp.async helpers ----------------
__device__ __forceinline__ void cpasync16(void* smem, const void* g) {
    unsigned sa = (unsigned)__cvta_generic_to_shared(smem);
    asm volatile("cp.async.cg.shared.global [%0], [%1], 16;" :: "r"(sa), "l"(g));
}
__device__ __forceinline__ void cp_commit() { asm volatile("cp.async.commit_group;"); }
__device__ __forceinline__ void cp_wait0()  { asm volatile("cp.async.wait_group 0;"); }

// ---------------- device scratch ----------------
__device__ float g_dec[BQ * ATTD];
__device__ float g_encR[(size_t)BQ * 64 * HD];
__device__ int   g_rowb[BQ * 64];
__device__ int   g_base[BQ];
__device__ int   g_nnz[BQ];
__device__ float g_scoreR[BQ * 64];
__device__ int   g_R;
__device__ float g_empty[BQ];
__device__ float g_ctxemb[BQ * PADK];
__device__ float g_WoutP[PADK * ATTD];
__device__ float g_out[BQ * ATTD];
__device__ float g_x[BQ * ATTD];
__device__ float g_bnsum[ATTD];
__device__ float g_bnsum2[ATTD];
__device__ float g_bna[ATTD];
__device__ float g_bnb[ATTD];

// ---------------- prep: pad W_out + zero counters ----------------
__global__ void k_prep(const float* __restrict__ Wout) {
    int idx = blockIdx.x * blockDim.x + threadIdx.x;
    if (idx < PADK * ATTD) g_WoutP[idx] = ((idx >> 10) < 68) ? Wout[idx] : 0.f;
    if (idx < ATTD) { g_bnsum[idx] = 0.f; g_bnsum2[idx] = 0.f; }
    if (idx < BQ) g_empty[idx] = 0.f;
    if (idx == 0) g_R = 0;
}

// ---------------- social pooling + compaction (256 thr/anchor) ----------------
__global__ void k_pool(const float* __restrict__ h, const float* __restrict__ end_pos) {
    int b = blockIdx.x;
    int s = b >> 6;
    int i = b & 63;
    int tid = threadIdx.x;      // 256
    int d = tid & 63;
    int g = tid >> 6;

    __shared__ __align__(16) float hsh[4096];
    __shared__ __align__(16) float acc[4096];
    __shared__ float px[64], py[64];
    __shared__ int   cellj[64];
    __shared__ int   nz[64];
    __shared__ int   slot_cell[64];
    __shared__ int   sh_base, sh_n;

    for (int t = tid; t < 1024; t += 256) {
        *(float4*)&hsh[t * 4] = *(const float4*)(h + (size_t)s * 4096 + t * 4);
        *(float4*)&acc[t * 4] = make_float4(0.f, 0.f, 0.f, 0.f);
    }
    if (tid < 64) {
        px[tid] = end_pos[(s * 64 + tid) * 2 + 0];
        py[tid] = end_pos[(s * 64 + tid) * 2 + 1];
        nz[tid] = 0;
    }
    __syncthreads();

    if (tid < 64) {
        float ax = px[i], ay = py[i];
        float tlx = ax - 1.0f, tly = ay + 1.0f;
        float brx = ax + 1.0f, bry = ay - 1.0f;
        float ox = px[tid], oy = py[tid];
        bool oob = (ox >= brx) || (ox <= tlx) || (oy >= tly) || (oy <= bry) || (tid == i);
        int c = -1;
        if (!oob) {
            float cx = floorf((ox - tlx) / 2.0f * 8.0f);
            float cy = floorf((tly - oy) / 2.0f * 8.0f);
            c = (int)(cx + cy * 8.0f);
        }
        cellj[tid] = c;
    }
    __syncthreads();

    for (int j = g * 16; j < g * 16 + 16; j++) {
        int c = cellj[j];
        if (c >= 0) {
            atomicAdd(&acc[c * 64 + d], hsh[j * 64 + d]);
            if (d == 0) nz[c] = 1;
        }
    }
    __syncthreads();

    if (tid == 0) {
        int n = 0;
        for (int c = 0; c < 64; c++) if (nz[c]) slot_cell[n++] = c;
        int base = atomicAdd(&g_R, n);
        sh_base = base; sh_n = n;
        g_base[b] = base; g_nnz[b] = n;
    }
    __syncthreads();

    int base = sh_base, n = sh_n;
    for (int t = g; t < n; t += 4) {
        int c = slot_cell[t];
        g_encR[(size_t)(base + t) * 64 + d] = acc[c * 64 + d];
        if (d == 0) g_rowb[base + t] = b;
    }
}

// ---------------- pipelined fp32x2 SGEMM (R3 mainloop) ----------------
// C = act(A[M,K]@B[K,N] + bias); 128x128 tile, 256 thr, 2-stage cp.async,
// 8x8 micro, FFMA2 with f2rep-built A operands.
// EMPTY: also accumulate relu(C + benc).wfull per row into empty_out.
// BN: also accumulate per-column sum/sum2 of C into g_bnsum/g_bnsum2.
template<int RELU, int EMPTY, int BN>
__global__ void __launch_bounds__(256) k_sgemm(const float* __restrict__ A,
                                               const float* __restrict__ B,
                                               const float* __restrict__ bias,
                                               float* __restrict__ C,
                                               int N, int K,
                                               const float* __restrict__ benc,
                                               const float* __restrict__ wfull,
                                               float* __restrict__ empty_out) {
    __shared__ __align__(16) float As[2][128][16];
    __shared__ __align__(16) float Bs[2][16][128];
    __shared__ float bnS[128], bnS2[128];
    int tid = threadIdx.x;
    int m0 = blockIdx.y * 128;
    int n0 = blockIdx.x * 128;
    int tr = tid >> 4, tc = tid & 15;
    int KT = K >> 4;

    if (BN && tid < 128) { bnS[tid] = 0.f; bnS2[tid] = 0.f; }

    auto stage_load = [&](int st, int k0) {
#pragma unroll
        for (int q = 0; q < 2; q++) {
            int c = tid + q * 256;           // 0..511
            int ar = c >> 2, ak = (c & 3) * 4;
            cpasync16(&As[st][ar][ak], A + (size_t)(m0 + ar) * K + k0 + ak);
            int bk = c >> 5, bc = (c & 31) * 4;
            cpasync16(&Bs[st][bk][bc], B + (size_t)(k0 + bk) * N + n0 + bc);
        }
    };

    ull acc[8][4];
#pragma unroll
    for (int i = 0; i < 8; i++)
#pragma unroll
        for (int j = 0; j < 4; j++) acc[i][j] = 0ull;

    stage_load(0, 0);
    cp_commit();

    for (int it = 0; it < KT; it++) {
        int cur = it & 1;
        cp_wait0();
        __syncthreads();
        if (it + 1 < KT) stage_load(cur ^ 1, (it + 1) * 16);
        cp_commit();

#pragma unroll
        for (int kg = 0; kg < 4; kg++) {
            float4 ar[8];
#pragma unroll
            for (int i = 0; i < 4; i++) {
                ar[i]     = *(float4*)&As[cur][tr * 4 + i][kg * 4];
                ar[4 + i] = *(float4*)&As[cur][64 + tr * 4 + i][kg * 4];
            }
#pragma unroll
            for (int kk = 0; kk < 4; kk++) {
                int k = kg * 4 + kk;
                ulonglong2 b0 = *(ulonglong2*)&Bs[cur][k][tc * 4];
                ulonglong2 b1 = *(ulonglong2*)&Bs[cur][k][64 + tc * 4];
#pragma unroll
                for (int i = 0; i < 8; i++) {
                    ull ap = f2rep(((const float*)&ar[i])[kk]);
                    ffma2(acc[i][0], ap, b0.x); ffma2(acc[i][1], ap, b0.y);
                    ffma2(acc[i][2], ap, b1.x); ffma2(acc[i][3], ap, b1.y);
                }
            }
        }
        __syncthreads();
    }

    float4 bv0 = *(const float4*)(bias + n0 + tc * 4);
    float4 bv1 = *(const float4*)(bias + n0 + 64 + tc * 4);
    float4 be0 = make_float4(0.f, 0.f, 0.f, 0.f), be1 = be0, wf0 = be0, wf1 = be0;
    if (EMPTY) {
        be0 = *(const float4*)(benc + n0 + tc * 4);
        be1 = *(const float4*)(benc + n0 + 64 + tc * 4);
        wf0 = *(const float4*)(wfull + n0 + tc * 4);
        wf1 = *(const float4*)(wfull + n0 + 64 + tc * 4);
    }
    float4 cs0 = make_float4(0.f, 0.f, 0.f, 0.f), cs1 = cs0, cq0 = cs0, cq1 = cs0;
#pragma unroll
    for (int i = 0; i < 8; i++) {
        int m = m0 + ((i < 4) ? (tr * 4 + i) : (64 + tr * 4 + i - 4));
        float2 p0 = f2unpack(acc[i][0]);
        float2 p1 = f2unpack(acc[i][1]);
        float2 p2 = f2unpack(acc[i][2]);
        float2 p3 = f2unpack(acc[i][3]);
        float4 o0 = make_float4(p0.x + bv0.x, p0.y + bv0.y, p1.x + bv0.z, p1.y + bv0.w);
        float4 o1 = make_float4(p2.x + bv1.x, p2.y + bv1.y, p3.x + bv1.z, p3.y + bv1.w);
        if (RELU) {
            o0.x = fmaxf(o0.x, 0.f); o0.y = fmaxf(o0.y, 0.f); o0.z = fmaxf(o0.z, 0.f); o0.w = fmaxf(o0.w, 0.f);
            o1.x = fmaxf(o1.x, 0.f); o1.y = fmaxf(o1.y, 0.f); o1.z = fmaxf(o1.z, 0.f); o1.w = fmaxf(o1.w, 0.f);
        }
        *(float4*)(C + (size_t)m * N + n0 + tc * 4)      = o0;
        *(float4*)(C + (size_t)m * N + n0 + 64 + tc * 4) = o1;
        if (BN) {
            cs0.x += o0.x; cs0.y += o0.y; cs0.z += o0.z; cs0.w += o0.w;
            cs1.x += o1.x; cs1.y += o1.y; cs1.z += o1.z; cs1.w += o1.w;
            cq0.x += o0.x * o0.x; cq0.y += o0.y * o0.y; cq0.z += o0.z * o0.z; cq0.w += o0.w * o0.w;
            cq1.x += o1.x * o1.x; cq1.y += o1.y * o1.y; cq1.z += o1.z * o1.z; cq1.w += o1.w * o1.w;
        }
        if (EMPTY) {
            float r = 0.f, v;
            v = o0.x + be0.x; if (v > 0.f) r += v * wf0.x;
            v = o0.y + be0.y; if (v > 0.f) r += v * wf0.y;
            v = o0.z + be0.z; if (v > 0.f) r += v * wf0.z;
            v = o0.w + be0.w; if (v > 0.f) r += v * wf0.w;
            v = o1.x + be1.x; if (v > 0.f) r += v * wf1.x;
            v = o1.y + be1.y; if (v > 0.f) r += v * wf1.y;
            v = o1.z + be1.z; if (v > 0.f) r += v * wf1.z;
            v = o1.w + be1.w; if (v > 0.f) r += v * wf1.w;
            r += __shfl_xor_sync(0xffffffffu, r, 1);
            r += __shfl_xor_sync(0xffffffffu, r, 2);
            r += __shfl_xor_sync(0xffffffffu, r, 4);
            r += __shfl_xor_sync(0xffffffffu, r, 8);
            if (tc == 0) atomicAdd(&empty_out[m], r);
        }
    }
    if (BN) {
        atomicAdd(&bnS [tc * 4 + 0], cs0.x); atomicAdd(&bnS [tc * 4 + 1], cs0.y);
        atomicAdd(&bnS [tc * 4 + 2], cs0.z); atomicAdd(&bnS [tc * 4 + 3], cs0.w);
        atomicAdd(&bnS [64 + tc * 4 + 0], cs1.x); atomicAdd(&bnS [64 + tc * 4 + 1], cs1.y);
        atomicAdd(&bnS [64 + tc * 4 + 2], cs1.z); atomicAdd(&bnS [64 + tc * 4 + 3], cs1.w);
        atomicAdd(&bnS2[tc * 4 + 0], cq0.x); atomicAdd(&bnS2[tc * 4 + 1], cq0.y);
        atomicAdd(&bnS2[tc * 4 + 2], cq0.z); atomicAdd(&bnS2[tc * 4 + 3], cq0.w);
        atomicAdd(&bnS2[64 + tc * 4 + 0], cq1.x); atomicAdd(&bnS2[64 + tc * 4 + 1], cq1.y);
        atomicAdd(&bnS2[64 + tc * 4 + 2], cq1.z); atomicAdd(&bnS2[64 + tc * 4 + 3], cq1.w);
        __syncthreads();
        if (tid < 128) {
            atomicAdd(&g_bnsum [n0 + tid], bnS [tid]);
            atomicAdd(&g_bnsum2[n0 + tid], bnS2[tid]);
        }
    }
}

// ---------------- fused sparse score GEMM (literal R3 version) ---------------
// score[r] = sum_a relu(enc_r . Wenc[:,a] + benc[a] + dec[rowb[r],a]) * wfull[a] + bfull
__global__ void __launch_bounds__(256) k_scores(const float* __restrict__ Wenc,
                                                const float* __restrict__ benc,
                                                const float* __restrict__ wfull,
                                                const float* __restrict__ bfull) {
    int R = g_R;
    int r0 = blockIdx.x * 64;
    if (r0 >= R) return;

    __shared__ __align__(16) float As[64][68];   // [k][row]
    __shared__ __align__(16) float Bs[2][16][128];
    __shared__ int   rb[64];
    __shared__ float ws[1024], bes[1024];
    __shared__ float red[64][17];

    int tid = threadIdx.x;  // 256
    int tr = tid >> 4, tc = tid & 15;

    // A tile load + transpose (64 rows x 64 k)
#pragma unroll
    for (int it = 0; it < 4; it++) {
        int t = tid + it * 256;
        int row = t >> 4;
        int kq = (t & 15) * 4;
        float4 v = make_float4(0.f, 0.f, 0.f, 0.f);
        if (r0 + row < R) v = *(const float4*)(g_encR + (size_t)(r0 + row) * 64 + kq);
        As[kq + 0][row] = v.x; As[kq + 1][row] = v.y;
        As[kq + 2][row] = v.z; As[kq + 3][row] = v.w;
    }
    if (tid < 64) rb[tid] = (r0 + tid < R) ? g_rowb[r0 + tid] : 0;
    for (int i = tid; i < 1024; i += 256) { ws[i] = wfull[i]; bes[i] = benc[i]; }

    // Wenc streaming: 32 tiles of 16x128 (t = ct*4 + ks)
    auto stage_load = [&](int st, int t) {
#pragma unroll
        for (int q = 0; q < 2; q++) {
            int c = tid + q * 256;
            int kr = c >> 5, cc = (c & 31) * 4;
            cpasync16(&Bs[st][kr][cc],
                      Wenc + (size_t)((t & 3) * 16 + kr) * 1024 + (t >> 2) * 128 + cc);
        }
    };

    float rowsum[4] = {0.f, 0.f, 0.f, 0.f};
    ull acc[4][4];

    stage_load(0, 0);
    cp_commit();

    for (int t = 0; t < 32; t++) {
        int cur = t & 1;
        int ks = t & 3, ct = t >> 2;
        cp_wait0();
        __syncthreads();
        if (t + 1 < 32) stage_load(cur ^ 1, t + 1);
        cp_commit();

        if (ks == 0) {
#pragma unroll
            for (int i = 0; i < 4; i++)
#pragma unroll
                for (int j = 0; j < 4; j++) acc[i][j] = 0ull;
        }

#pragma unroll
        for (int k = 0; k < 16; k++) {
            int kk = ks * 16 + k;
            float4 a = *(float4*)&As[kk][tr * 4];
            ulonglong2 b0 = *(ulonglong2*)&Bs[cur][k][tc * 4];
            ulonglong2 b1 = *(ulonglong2*)&Bs[cur][k][64 + tc * 4];
            ull ap;
            ap = f2rep(a.x); ffma2(acc[0][0], ap, b0.x); ffma2(acc[0][1], ap, b0.y); ffma2(acc[0][2], ap, b1.x); ffma2(acc[0][3], ap, b1.y);
            ap = f2rep(a.y); ffma2(acc[1][0], ap, b0.x); ffma2(acc[1][1], ap, b0.y); ffma2(acc[1][2], ap, b1.x); ffma2(acc[1][3], ap, b1.y);
            ap = f2rep(a.z); ffma2(acc[2][0], ap, b0.x); ffma2(acc[2][1], ap, b0.y); ffma2(acc[2][2], ap, b1.x); ffma2(acc[2][3], ap, b1.y);
            ap = f2rep(a.w); ffma2(acc[3][0], ap, b0.x); ffma2(acc[3][1], ap, b0.y); ffma2(acc[3][2], ap, b1.x); ffma2(acc[3][3], ap, b1.y);
        }

        if (ks == 3) {
            int n0 = ct * 128;
#pragma unroll
            for (int i = 0; i < 4; i++) {
                int brow = rb[tr * 4 + i];
                const float* decrow = g_dec + (size_t)brow * 1024 + n0;
                float4 d0 = *(const float4*)(decrow + tc * 4);
                float4 d1 = *(const float4*)(decrow + 64 + tc * 4);
                float2 p0 = f2unpack(acc[i][0]);
                float2 p1 = f2unpack(acc[i][1]);
                float2 p2 = f2unpack(acc[i][2]);
                float2 p3 = f2unpack(acc[i][3]);
                int c0 = n0 + tc * 4, c1 = n0 + 64 + tc * 4;
                float v;
                v = p0.x + bes[c0 + 0] + d0.x; if (v > 0.f) rowsum[i] += v * ws[c0 + 0];
                v = p0.y + bes[c0 + 1] + d0.y; if (v > 0.f) rowsum[i] += v * ws[c0 + 1];
                v = p1.x + bes[c0 + 2] + d0.z; if (v > 0.f) rowsum[i] += v * ws[c0 + 2];
                v = p1.y + bes[c0 + 3] + d0.w; if (v > 0.f) rowsum[i] += v * ws[c0 + 3];
                v = p2.x + bes[c1 + 0] + d1.x; if (v > 0.f) rowsum[i] += v * ws[c1 + 0];
                v = p2.y + bes[c1 + 1] + d1.y; if (v > 0.f) rowsum[i] += v * ws[c1 + 1];
                v = p3.x + bes[c1 + 2] + d1.z; if (v > 0.f) rowsum[i] += v * ws[c1 + 2];
                v = p3.y + bes[c1 + 3] + d1.w; if (v > 0.f) rowsum[i] += v * ws[c1 + 3];
            }
        }
    }

#pragma unroll
    for (int i = 0; i < 4; i++) red[tr * 4 + i][tc] = rowsum[i];
    __syncthreads();
    if (tid < 64) {
        float ssum = 0.f;
#pragma unroll
        for (int c = 0; c < 16; c++) ssum += red[tid][c];
        if (r0 + tid < R) g_scoreR[r0 + tid] = ssum + bfull[0];
    }
}

// ---------------- softmax + ctx + embed (64 thr/anchor) ----------------
__global__ void k_softctx(const float* __restrict__ bfull, const float* __restrict__ end_pos,
                          const float* __restrict__ rel_pos, const float* __restrict__ Wemb,
                          const float* __restrict__ bemb) {
    int b = blockIdx.x;
    int tid = threadIdx.x;  // 64
    __shared__ float sc[64];
    __shared__ float alpha[64];

    int base = g_base[b], nnz = g_nnz[b];
    if (tid < nnz) sc[tid] = g_scoreR[base + tid];
    __syncthreads();
    if (tid == 0) {
        float se = g_empty[b] + bfull[0];
        float m = se;
        for (int t = 0; t < nnz; t++) m = fmaxf(m, sc[t]);
        float Z = (float)(64 - nnz) * expf(se - m);
        for (int t = 0; t < nnz; t++) { float e = expf(sc[t] - m); alpha[t] = e; Z += e; }
        float inv = 1.0f / Z;
        for (int t = 0; t < nnz; t++) alpha[t] *= inv;
    }
    __syncthreads();

    float c = 0.f;
    for (int t = 0; t < nnz; t++) c += alpha[t] * g_encR[(size_t)(base + t) * 64 + tid];
    g_ctxemb[b * PADK + tid] = c;

    if (tid < 4) {
        float v = end_pos[b * 2 + 0] * Wemb[0 * 4 + tid] + end_pos[b * 2 + 1] * Wemb[1 * 4 + tid]
                + rel_pos[b * 2 + 0] * Wemb[2 * 4 + tid] + rel_pos[b * 2 + 1] * Wemb[3 * 4 + tid]
                + bemb[tid];
        g_ctxemb[b * PADK + 64 + tid] = v > 0.f ? v : 0.f;
    } else if (tid < 16) {
        g_ctxemb[b * PADK + 64 + tid] = 0.f;
    }
}

// ---------------- batchnorm final + apply --------
__global__ void k_bnfinal(const float* __restrict__ gamma, const float* __restrict__ beta) {
    int c = threadIdx.x;
    float mu = g_bnsum[c] / (float)BQ;
    float var = g_bnsum2[c] / (float)BQ - mu * mu;
    float rstd = rsqrtf(var + 1e-5f);
    float ga = gamma[c] * rstd;
    g_bna[c] = ga;
    g_bnb[c] = beta[c] - mu * ga;
}

__global__ void k_bnapply(float* __restrict__ out) {
    int idx = blockIdx.x * blockDim.x + threadIdx.x;
    if (idx < BQ * ATTD) {
        int c = idx & 1023;
        float v = g_x[idx] * g_bna[c] + g_bnb[c];
        out[idx] = v > 0.f ? v : 0.f;
    }
}

// ---------------- launch ----------------
extern "C" void kernel_launch(void* const* d_in, const int* in_sizes, int n_in,
                              void* d_out, int out_size) {
    const float* h       = (const float*)d_in[0];
    const float* end_pos = (const float*)d_in[2];
    const float* rel_pos = (const float*)d_in[3];
    const float* Wenc    = (const float*)d_in[4];
    const float* benc    = (const float*)d_in[5];
    const float* Wdec    = (const float*)d_in[6];
    const float* bdec    = (const float*)d_in[7];
    const float* wfull   = (const float*)d_in[8];
    const float* bfull   = (const float*)d_in[9];
    const float* Wemb    = (const float*)d_in[10];
    const float* bemb    = (const float*)d_in[11];
    const float* Wout    = (const float*)d_in[12];
    const float* bout    = (const float*)d_in[13];
    const float* Wmlp    = (const float*)d_in[14];
    const float* bmlp    = (const float*)d_in[15];
    const float* gamma   = (const float*)d_in[16];
    const float* beta    = (const float*)d_in[17];
    float* out = (float*)d_out;

    float *p_dec, *p_ctxemb, *p_WoutP, *p_out, *p_x, *p_empty;
    cudaGetSymbolAddress((void**)&p_dec,    g_dec);
    cudaGetSymbolAddress((void**)&p_ctxemb, g_ctxemb);
    cudaGetSymbolAddress((void**)&p_WoutP,  g_WoutP);
    cudaGetSymbolAddress((void**)&p_out,    g_out);
    cudaGetSymbolAddress((void**)&p_x,      g_x);
    cudaGetSymbolAddress((void**)&p_empty,  g_empty);

    dim3 gg(ATTD / 128, BQ / 128);   // (8, 16) = 128 blocks

    k_prep<<<(PADK * ATTD + 255) / 256, 256>>>(Wout);
    k_pool<<<BQ, 256>>>(h, end_pos);
    k_sgemm<0, 1, 0><<<gg, 256>>>(h, Wdec, bdec, p_dec, ATTD, HD, benc, wfull, p_empty);
    k_scores<<<BQ, 256>>>(Wenc, benc, wfull, bfull);
    k_softctx<<<BQ, 64>>>(bfull, end_pos, rel_pos, Wemb, bemb);
    k_sgemm<1, 0, 0><<<gg, 256>>>(p_ctxemb, p_WoutP, bout, p_out, ATTD, PADK, nullptr, nullptr, nullptr);
    k_sgemm<0, 0, 1><<<gg, 256>>>(p_out, Wmlp, bmlp, p_x, ATTD, ATTD, nullptr, nullptr, nullptr);
    k_bnfinal<<<1, 1024>>>(gamma, beta);
    k_bnapply<<<(BQ * ATTD + 255) / 256, 256>>>(out);
}

// round 10
// speedup vs baseline: 1.5178x; 1.2960x over previous
#include <cuda_runtime.h>
#include <cuda_bf16.h>
#include <stdint.h>
#include <math.h>

#define BQ   2048
#define HD   64
#define ATTD 1024

typedef unsigned long long ull;

// ================= scalar FFMA2 helpers (k_scores) =================
__device__ __forceinline__ void ffma2(ull& d, ull a, ull b) {
    asm("fma.rn.f32x2 %0, %1, %2, %0;" : "+l"(d) : "l"(a), "l"(b));
}
__device__ __forceinline__ ull f2rep(float x) {
    ull r; asm("mov.b64 %0, {%1, %1};" : "=l"(r) : "f"(x)); return r;
}
__device__ __forceinline__ float2 f2unpack(ull v) {
    float2 r; asm("mov.b64 {%0, %1}, %2;" : "=f"(r.x), "=f"(r.y) : "l"(v)); return r;
}
// ================= cp.async =================
__device__ __forceinline__ void cpasync16(void* smem, const void* g) {
    unsigned sa = (unsigned)__cvta_generic_to_shared(smem);
    asm volatile("cp.async.cg.shared.global [%0], [%1], 16;" :: "r"(sa), "l"(g));
}
__device__ __forceinline__ void cpasync16s(unsigned saddr, const void* g) {
    asm volatile("cp.async.cg.shared.global [%0], [%1], 16;" :: "r"(saddr), "l"(g));
}
__device__ __forceinline__ void cp_commit() { asm volatile("cp.async.commit_group;"); }
__device__ __forceinline__ void cp_wait0()  { asm volatile("cp.async.wait_group 0;"); }
__device__ __forceinline__ void cp_wait1()  { asm volatile("cp.async.wait_group 1;"); }

__device__ __forceinline__ unsigned smem_u32(const void* p) {
    return (unsigned)__cvta_generic_to_shared(p);
}

// ================= HMMA (mma.sync, baseline sm_80+ features) =================
#define LDSM4(r, a) asm volatile( \
    "ldmatrix.sync.aligned.m8n8.x4.shared.b16 {%0,%1,%2,%3}, [%4];" \
    : "=r"((r)[0]), "=r"((r)[1]), "=r"((r)[2]), "=r"((r)[3]) : "r"(a))

#define MMA16816(d, a, b) asm volatile( \
    "mma.sync.aligned.m16n8k16.row.col.f32.bf16.bf16.f32 " \
    "{%0,%1,%2,%3}, {%4,%5,%6,%7}, {%8,%9}, {%0,%1,%2,%3};" \
    : "+f"((d)[0]), "+f"((d)[1]), "+f"((d)[2]), "+f"((d)[3]) \
    : "r"((a)[0]), "r"((a)[1]), "r"((a)[2]), "r"((a)[3]), "r"((b)[0]), "r"((b)[1]))

// ================= device scratch =================
__device__ float g_dec[BQ * ATTD];
__device__ float g_encR[(size_t)BQ * 64 * HD];
__device__ int   g_rowb[BQ * 64];
__device__ int   g_base[BQ];
__device__ int   g_nnz[BQ];
__device__ float g_scoreR[BQ * 64];
__device__ int   g_R;
__device__ float g_empty[BQ];
__device__ float g_x[BQ * ATTD];
__device__ float g_bnsum[ATTD];
__device__ float g_bnsum2[ATTD];
__device__ float g_bna[ATTD];
__device__ float g_bnb[ATTD];
// bf16 split operands (16B aligned for cp.async)
__device__ __align__(16) __nv_bfloat16 g_hAh[BQ * 64],     g_hAl[BQ * 64];
__device__ __align__(16) __nv_bfloat16 g_cAh[BQ * 128],    g_cAl[BQ * 128];
__device__ __align__(16) __nv_bfloat16 g_mAh[BQ * 1024],   g_mAl[BQ * 1024];
__device__ __align__(16) __nv_bfloat16 g_WdH[1024 * 64],   g_WdL[1024 * 64];
__device__ __align__(16) __nv_bfloat16 g_WoH[1024 * 128],  g_WoL[1024 * 128];
__device__ __align__(16) __nv_bfloat16 g_WmH[1024 * 1024], g_WmL[1024 * 1024];

// ================= prep =================
__global__ void k_prep() {
    int idx = blockIdx.x * blockDim.x + threadIdx.x;
    if (idx < ATTD) { g_bnsum[idx] = 0.f; g_bnsum2[idx] = 0.f; }
    if (idx < BQ) g_empty[idx] = 0.f;
    if (idx == 0) g_R = 0;
}

// ================= fp32 -> bf16 hi/lo split =================
__global__ void k_splitA(const float* __restrict__ A, __nv_bfloat16* __restrict__ Ah,
                         __nv_bfloat16* __restrict__ Al, int n) {
    int i = blockIdx.x * blockDim.x + threadIdx.x;
    if (i < n) {
        float v = A[i];
        __nv_bfloat16 hi = __float2bfloat16(v);
        Ah[i] = hi;
        Al[i] = __float2bfloat16(v - __bfloat162float(hi));
    }
}

// ======= weight split + transpose: W[KV<=KK rows][1024] -> Bt[1024][KK] =======
__global__ void k_splitB(const float* __restrict__ W, __nv_bfloat16* __restrict__ Bh,
                         __nv_bfloat16* __restrict__ Bl, int KK, int KV) {
    __shared__ float t[32][33];
    int n0 = blockIdx.x * 32, k0 = blockIdx.y * 32;
    int tx = threadIdx.x, ty = threadIdx.y;   // 32 x 8
#pragma unroll
    for (int i = 0; i < 4; i++) {
        int k = k0 + ty + i * 8;
        t[ty + i * 8][tx] = (k < KV) ? W[(size_t)k * 1024 + n0 + tx] : 0.f;
    }
    __syncthreads();
#pragma unroll
    for (int i = 0; i < 4; i++) {
        int n = n0 + ty + i * 8;
        float v = t[tx][ty + i * 8];
        __nv_bfloat16 hi = __float2bfloat16(v);
        Bh[(size_t)n * KK + k0 + tx] = hi;
        Bl[(size_t)n * KK + k0 + tx] = __float2bfloat16(v - __bfloat162float(hi));
    }
}

// ================= social pooling + compaction =================
__global__ void k_pool(const float* __restrict__ h, const float* __restrict__ end_pos) {
    int b = blockIdx.x;
    int s = b >> 6;
    int i = b & 63;
    int tid = threadIdx.x;      // 256
    int d = tid & 63;
    int g = tid >> 6;

    __shared__ __align__(16) float hsh[4096];
    __shared__ __align__(16) float acc[4096];
    __shared__ float px[64], py[64];
    __shared__ int   cellj[64];
    __shared__ int   nz[64];
    __shared__ int   slot_cell[64];
    __shared__ int   sh_base, sh_n;

    for (int t = tid; t < 1024; t += 256) {
        *(float4*)&hsh[t * 4] = *(const float4*)(h + (size_t)s * 4096 + t * 4);
        *(float4*)&acc[t * 4] = make_float4(0.f, 0.f, 0.f, 0.f);
    }
    if (tid < 64) {
        px[tid] = end_pos[(s * 64 + tid) * 2 + 0];
        py[tid] = end_pos[(s * 64 + tid) * 2 + 1];
        nz[tid] = 0;
    }
    __syncthreads();

    if (tid < 64) {
        float ax = px[i], ay = py[i];
        float tlx = ax - 1.0f, tly = ay + 1.0f;
        float brx = ax + 1.0f, bry = ay - 1.0f;
        float ox = px[tid], oy = py[tid];
        bool oob = (ox >= brx) || (ox <= tlx) || (oy >= tly) || (oy <= bry) || (tid == i);
        int c = -1;
        if (!oob) {
            float cx = floorf((ox - tlx) / 2.0f * 8.0f);
            float cy = floorf((tly - oy) / 2.0f * 8.0f);
            c = (int)(cx + cy * 8.0f);
        }
        cellj[tid] = c;
    }
    __syncthreads();

    for (int j = g * 16; j < g * 16 + 16; j++) {
        int c = cellj[j];
        if (c >= 0) {
            atomicAdd(&acc[c * 64 + d], hsh[j * 64 + d]);
            if (d == 0) nz[c] = 1;
        }
    }
    __syncthreads();

    if (tid == 0) {
        int n = 0;
        for (int c = 0; c < 64; c++) if (nz[c]) slot_cell[n++] = c;
        int base = atomicAdd(&g_R, n);
        sh_base = base; sh_n = n;
        g_base[b] = base; g_nnz[b] = n;
    }
    __syncthreads();

    int base = sh_base, n = sh_n;
    for (int t = g; t < n; t += 4) {
        int c = slot_cell[t];
        g_encR[(size_t)(base + t) * 64 + d] = acc[c * 64 + d];
        if (d == 0) g_rowb[base + t] = b;
    }
}

// ================= HMMA bf16-split GEMM =================
// C[M,1024] = A[M,K] @ B[K,1024]; A hi/lo [M][K], Bt hi/lo [1024][K] (k-contig).
// mma m16n8k16 row.col: A row-major, B col-major == Bt rows.
// CTA 128x128, 8 warps 2(M)x4(N), warp tile 64x32. K chunks of 64, 2-stage cp.async.
// EPI 0: f32 out + EMPTY (dec). EPI 1: relu -> bf16 hi/lo (out). EPI 2: f32 + BN (mlp).
#define RSTR  72                      // padded row stride, elements
#define MATB  (128 * RSTR * 2)        // 18432 B per matrix tile
#define STAGEB (4 * MATB)             // 73728 B per stage
template<int EPI>
__global__ void __launch_bounds__(256) hm_gemm(
    const __nv_bfloat16* __restrict__ Ah, const __nv_bfloat16* __restrict__ Al,
    const __nv_bfloat16* __restrict__ Bh, const __nv_bfloat16* __restrict__ Bl,
    const float* __restrict__ bias, int K,
    float* __restrict__ Cf,
    __nv_bfloat16* __restrict__ Coh, __nv_bfloat16* __restrict__ Col,
    const float* __restrict__ benc, const float* __restrict__ wfull,
    float* __restrict__ empty_out)
{
    extern __shared__ __align__(128) char dsm[];
    unsigned sbase = smem_u32(dsm);
    int tid = threadIdx.x;
    int lane = tid & 31, wid = tid >> 5;
    int m0 = blockIdx.y * 128, n0 = blockIdx.x * 128;
    int mb = (wid >> 2) * 64;      // warp M base in tile
    int nb = (wid & 3) * 32;       // warp N base in tile
    int NC = K >> 6;

    const __nv_bfloat16* gA_h = Ah + (size_t)m0 * K;
    const __nv_bfloat16* gA_l = Al + (size_t)m0 * K;
    const __nv_bfloat16* gB_h = Bh + (size_t)n0 * K;
    const __nv_bfloat16* gB_l = Bl + (size_t)n0 * K;

    auto stage_load = [&](int st, int kc) {
        unsigned so = sbase + st * STAGEB;
        const __nv_bfloat16* gs;
#pragma unroll
        for (int mat = 0; mat < 4; mat++) {
            gs = (mat == 0) ? gA_h : (mat == 1) ? gA_l : (mat == 2) ? gB_h : gB_l;
#pragma unroll
            for (int q = 0; q < 4; q++) {
                int idx = tid + q * 256;      // 0..1023
                int r = idx >> 3, c = idx & 7;
                cpasync16s(so + mat * MATB + r * (RSTR * 2) + c * 16,
                           gs + (size_t)r * K + kc * 64 + c * 8);
            }
        }
    };

    float acc[4][4][4];
#pragma unroll
    for (int i = 0; i < 4; i++)
#pragma unroll
        for (int j = 0; j < 4; j++)
#pragma unroll
            for (int k = 0; k < 4; k++) acc[i][j][k] = 0.f;

    // ldmatrix per-lane address components
    int quad = lane >> 3, rin = lane & 7;
    int a_r = (quad & 1) * 8 + rin;        // + mb + mt*16
    int a_c = (quad >> 1) * 8;             // + ks*16
    int b_r = (quad >> 1) * 8 + rin;       // + nb + np*16
    int b_c = (quad & 1) * 8;              // + ks*16

    stage_load(0, 0);
    cp_commit();

    for (int ch = 0; ch < NC; ch++) {
        int st = ch & 1;
        if (ch + 1 < NC) { stage_load(st ^ 1, ch + 1); cp_commit(); cp_wait1(); }
        else cp_wait0();
        __syncthreads();
        unsigned so = sbase + st * STAGEB;

#pragma unroll
        for (int ks = 0; ks < 4; ks++) {
            unsigned fAh[4][4], fAl[4][4], fBh[2][4], fBl[2][4];
#pragma unroll
            for (int mt = 0; mt < 4; mt++) {
                unsigned ad = so + ((mb + mt * 16 + a_r) * RSTR + ks * 16 + a_c) * 2;
                LDSM4(fAh[mt], ad);
                LDSM4(fAl[mt], ad + MATB);
            }
#pragma unroll
            for (int np = 0; np < 2; np++) {
                unsigned bd = so + 2 * MATB + ((nb + np * 16 + b_r) * RSTR + ks * 16 + b_c) * 2;
                LDSM4(fBh[np], bd);
                LDSM4(fBl[np], bd + MATB);
            }
#pragma unroll
            for (int mt = 0; mt < 4; mt++)
#pragma unroll
                for (int nt = 0; nt < 4; nt++) {
                    unsigned* bh = &fBh[nt >> 1][(nt & 1) * 2];
                    unsigned* bl = &fBl[nt >> 1][(nt & 1) * 2];
                    MMA16816(acc[mt][nt], fAh[mt], bh);
                    MMA16816(acc[mt][nt], fAl[mt], bh);
                    MMA16816(acc[mt][nt], fAh[mt], bl);
                }
        }
        __syncthreads();
    }

    // ---- epilogue ----
    int g = lane >> 2;
    int cpos = (lane & 3) * 2;
    float cs[4][2], cq[4][2];
    if (EPI == 2) {
#pragma unroll
        for (int nt = 0; nt < 4; nt++) { cs[nt][0] = cs[nt][1] = 0.f; cq[nt][0] = cq[nt][1] = 0.f; }
    }

#pragma unroll
    for (int mt = 0; mt < 4; mt++) {
        int row = m0 + mb + mt * 16 + g;
        float e0 = 0.f, e1 = 0.f;
#pragma unroll
        for (int nt = 0; nt < 4; nt++) {
            int col = n0 + nb + nt * 8 + cpos;
            float b0v = bias[col], b1v = bias[col + 1];
            float v00 = acc[mt][nt][0] + b0v, v01 = acc[mt][nt][1] + b1v;
            float v10 = acc[mt][nt][2] + b0v, v11 = acc[mt][nt][3] + b1v;
            if (EPI == 1) {
                v00 = fmaxf(v00, 0.f); v01 = fmaxf(v01, 0.f);
                v10 = fmaxf(v10, 0.f); v11 = fmaxf(v11, 0.f);
                __nv_bfloat16 h00 = __float2bfloat16(v00), h01 = __float2bfloat16(v01);
                __nv_bfloat16 h10 = __float2bfloat16(v10), h11 = __float2bfloat16(v11);
                __nv_bfloat162 t;
                t.x = h00; t.y = h01;
                *(__nv_bfloat162*)&Coh[(size_t)row * 1024 + col] = t;
                t.x = h10; t.y = h11;
                *(__nv_bfloat162*)&Coh[(size_t)(row + 8) * 1024 + col] = t;
                t.x = __float2bfloat16(v00 - __bfloat162float(h00));
                t.y = __float2bfloat16(v01 - __bfloat162float(h01));
                *(__nv_bfloat162*)&Col[(size_t)row * 1024 + col] = t;
                t.x = __float2bfloat16(v10 - __bfloat162float(h10));
                t.y = __float2bfloat16(v11 - __bfloat162float(h11));
                *(__nv_bfloat162*)&Col[(size_t)(row + 8) * 1024 + col] = t;
            } else {
                float2 p;
                p.x = v00; p.y = v01;
                *(float2*)&Cf[(size_t)row * 1024 + col] = p;
                p.x = v10; p.y = v11;
                *(float2*)&Cf[(size_t)(row + 8) * 1024 + col] = p;
            }
            if (EPI == 0) {
                float be0 = benc[col], be1 = benc[col + 1];
                float wf0 = wfull[col], wf1 = wfull[col + 1];
                float t;
                t = v00 + be0; if (t > 0.f) e0 += t * wf0;
                t = v01 + be1; if (t > 0.f) e0 += t * wf1;
                t = v10 + be0; if (t > 0.f) e1 += t * wf0;
                t = v11 + be1; if (t > 0.f) e1 += t * wf1;
            }
            if (EPI == 2) {
                cs[nt][0] += v00 + v10; cs[nt][1] += v01 + v11;
                cq[nt][0] += v00 * v00 + v10 * v10;
                cq[nt][1] += v01 * v01 + v11 * v11;
            }
        }
        if (EPI == 0) {
            e0 += __shfl_xor_sync(0xffffffffu, e0, 1);
            e0 += __shfl_xor_sync(0xffffffffu, e0, 2);
            e1 += __shfl_xor_sync(0xffffffffu, e1, 1);
            e1 += __shfl_xor_sync(0xffffffffu, e1, 2);
            if ((lane & 3) == 0) {
                atomicAdd(&empty_out[row], e0);
                atomicAdd(&empty_out[row + 8], e1);
            }
        }
    }
    if (EPI == 2) {
#pragma unroll
        for (int nt = 0; nt < 4; nt++) {
#pragma unroll
            for (int j = 0; j < 2; j++) {
                float s = cs[nt][j], q = cq[nt][j];
                s += __shfl_xor_sync(0xffffffffu, s, 4);
                s += __shfl_xor_sync(0xffffffffu, s, 8);
                s += __shfl_xor_sync(0xffffffffu, s, 16);
                q += __shfl_xor_sync(0xffffffffu, q, 4);
                q += __shfl_xor_sync(0xffffffffu, q, 8);
                q += __shfl_xor_sync(0xffffffffu, q, 16);
                if (lane < 4) {
                    int col = n0 + nb + nt * 8 + cpos + j;
                    atomicAdd(&g_bnsum[col], s);
                    atomicAdd(&g_bnsum2[col], q);
                }
            }
        }
    }
}

// ================= fused sparse score GEMM (proven R3/R7 version) =============
__global__ void __launch_bounds__(256) k_scores(const float* __restrict__ Wenc,
                                                const float* __restrict__ benc,
                                                const float* __restrict__ wfull,
                                                const float* __restrict__ bfull) {
    int R = g_R;
    int r0 = blockIdx.x * 64;
    if (r0 >= R) return;

    __shared__ __align__(16) float As[64][68];
    __shared__ __align__(16) float Bs[2][16][128];
    __shared__ int   rb[64];
    __shared__ float ws[1024], bes[1024];
    __shared__ float red[64][17];

    int tid = threadIdx.x;
    int tr = tid >> 4, tc = tid & 15;

#pragma unroll
    for (int it = 0; it < 4; it++) {
        int t = tid + it * 256;
        int row = t >> 4;
        int kq = (t & 15) * 4;
        float4 v = make_float4(0.f, 0.f, 0.f, 0.f);
        if (r0 + row < R) v = *(const float4*)(g_encR + (size_t)(r0 + row) * 64 + kq);
        As[kq + 0][row] = v.x; As[kq + 1][row] = v.y;
        As[kq + 2][row] = v.z; As[kq + 3][row] = v.w;
    }
    if (tid < 64) rb[tid] = (r0 + tid < R) ? g_rowb[r0 + tid] : 0;
    for (int i = tid; i < 1024; i += 256) { ws[i] = wfull[i]; bes[i] = benc[i]; }

    auto stage_load = [&](int st, int t) {
#pragma unroll
        for (int q = 0; q < 2; q++) {
            int c = tid + q * 256;
            int kr = c >> 5, cc = (c & 31) * 4;
            cpasync16(&Bs[st][kr][cc],
                      Wenc + (size_t)((t & 3) * 16 + kr) * 1024 + (t >> 2) * 128 + cc);
        }
    };

    float rowsum[4] = {0.f, 0.f, 0.f, 0.f};
    ull acc[4][4];

    stage_load(0, 0);
    cp_commit();

    for (int t = 0; t < 32; t++) {
        int cur = t & 1;
        int ks = t & 3, ct = t >> 2;
        cp_wait0();
        __syncthreads();
        if (t + 1 < 32) stage_load(cur ^ 1, t + 1);
        cp_commit();

        if (ks == 0) {
#pragma unroll
            for (int i = 0; i < 4; i++)
#pragma unroll
                for (int j = 0; j < 4; j++) acc[i][j] = 0ull;
        }

#pragma unroll
        for (int k = 0; k < 16; k++) {
            int kk = ks * 16 + k;
            float4 a = *(float4*)&As[kk][tr * 4];
            ulonglong2 b0 = *(ulonglong2*)&Bs[cur][k][tc * 4];
            ulonglong2 b1 = *(ulonglong2*)&Bs[cur][k][64 + tc * 4];
            ull ap;
            ap = f2rep(a.x); ffma2(acc[0][0], ap, b0.x); ffma2(acc[0][1], ap, b0.y); ffma2(acc[0][2], ap, b1.x); ffma2(acc[0][3], ap, b1.y);
            ap = f2rep(a.y); ffma2(acc[1][0], ap, b0.x); ffma2(acc[1][1], ap, b0.y); ffma2(acc[1][2], ap, b1.x); ffma2(acc[1][3], ap, b1.y);
            ap = f2rep(a.z); ffma2(acc[2][0], ap, b0.x); ffma2(acc[2][1], ap, b0.y); ffma2(acc[2][2], ap, b1.x); ffma2(acc[2][3], ap, b1.y);
            ap = f2rep(a.w); ffma2(acc[3][0], ap, b0.x); ffma2(acc[3][1], ap, b0.y); ffma2(acc[3][2], ap, b1.x); ffma2(acc[3][3], ap, b1.y);
        }

        if (ks == 3) {
            int n0 = ct * 128;
#pragma unroll
            for (int i = 0; i < 4; i++) {
                int brow = rb[tr * 4 + i];
                const float* decrow = g_dec + (size_t)brow * 1024 + n0;
                float4 d0 = *(const float4*)(decrow + tc * 4);
                float4 d1 = *(const float4*)(decrow + 64 + tc * 4);
                float2 p0 = f2unpack(acc[i][0]);
                float2 p1 = f2unpack(acc[i][1]);
                float2 p2 = f2unpack(acc[i][2]);
                float2 p3 = f2unpack(acc[i][3]);
                int c0 = n0 + tc * 4, c1 = n0 + 64 + tc * 4;
                float v;
                v = p0.x + bes[c0 + 0] + d0.x; if (v > 0.f) rowsum[i] += v * ws[c0 + 0];
                v = p0.y + bes[c0 + 1] + d0.y; if (v > 0.f) rowsum[i] += v * ws[c0 + 1];
                v = p1.x + bes[c0 + 2] + d0.z; if (v > 0.f) rowsum[i] += v * ws[c0 + 2];
                v = p1.y + bes[c0 + 3] + d0.w; if (v > 0.f) rowsum[i] += v * ws[c0 + 3];
                v = p2.x + bes[c1 + 0] + d1.x; if (v > 0.f) rowsum[i] += v * ws[c1 + 0];
                v = p2.y + bes[c1 + 1] + d1.y; if (v > 0.f) rowsum[i] += v * ws[c1 + 1];
                v = p3.x + bes[c1 + 2] + d1.z; if (v > 0.f) rowsum[i] += v * ws[c1 + 2];
                v = p3.y + bes[c1 + 3] + d1.w; if (v > 0.f) rowsum[i] += v * ws[c1 + 3];
            }
        }
    }

#pragma unroll
    for (int i = 0; i < 4; i++) red[tr * 4 + i][tc] = rowsum[i];
    __syncthreads();
    if (tid < 64) {
        float ssum = 0.f;
#pragma unroll
        for (int c = 0; c < 16; c++) ssum += red[tid][c];
        if (r0 + tid < R) g_scoreR[r0 + tid] = ssum + bfull[0];
    }
}

// ================= softmax + ctx + embed -> bf16 split A for out-GEMM =========
__global__ void k_softctx(const float* __restrict__ bfull, const float* __restrict__ end_pos,
                          const float* __restrict__ rel_pos, const float* __restrict__ Wemb,
                          const float* __restrict__ bemb) {
    int b = blockIdx.x;
    int tid = threadIdx.x;  // 128
    __shared__ float sc[64];
    __shared__ float alpha[64];

    int base = g_base[b], nnz = g_nnz[b];
    if (tid < nnz) sc[tid] = g_scoreR[base + tid];
    __syncthreads();
    if (tid == 0) {
        float se = g_empty[b] + bfull[0];
        float m = se;
        for (int t = 0; t < nnz; t++) m = fmaxf(m, sc[t]);
        float Z = (float)(64 - nnz) * expf(se - m);
        for (int t = 0; t < nnz; t++) { float e = expf(sc[t] - m); alpha[t] = e; Z += e; }
        float inv = 1.0f / Z;
        for (int t = 0; t < nnz; t++) alpha[t] *= inv;
    }
    __syncthreads();

    float v = 0.f;
    if (tid < 64) {
        float c = 0.f;
        for (int t = 0; t < nnz; t++) c += alpha[t] * g_encR[(size_t)(base + t) * 64 + tid];
        v = c;
    } else if (tid < 68) {
        int j = tid - 64;
        float e = end_pos[b * 2 + 0] * Wemb[0 * 4 + j] + end_pos[b * 2 + 1] * Wemb[1 * 4 + j]
                + rel_pos[b * 2 + 0] * Wemb[2 * 4 + j] + rel_pos[b * 2 + 1] * Wemb[3 * 4 + j]
                + bemb[j];
        v = fmaxf(e, 0.f);
    }
    __nv_bfloat16 hi = __float2bfloat16(v);
    g_cAh[b * 128 + tid] = hi;
    g_cAl[b * 128 + tid] = __float2bfloat16(v - __bfloat162float(hi));
}

// ================= batchnorm final + apply =================
__global__ void k_bnfinal(const float* __restrict__ gamma, const float* __restrict__ beta) {
    int c = threadIdx.x;
    float mu = g_bnsum[c] / (float)BQ;
    float var = g_bnsum2[c] / (float)BQ - mu * mu;
    float rstd = rsqrtf(var + 1e-5f);
    float ga = gamma[c] * rstd;
    g_bna[c] = ga;
    g_bnb[c] = beta[c] - mu * ga;
}

__global__ void k_bnapply(float* __restrict__ out) {
    int idx = blockIdx.x * blockDim.x + threadIdx.x;
    if (idx < BQ * ATTD) {
        int c = idx & 1023;
        float v = g_x[idx] * g_bna[c] + g_bnb[c];
        out[idx] = v > 0.f ? v : 0.f;
    }
}

// ================= launch =================
extern "C" void kernel_launch(void* const* d_in, const int* in_sizes, int n_in,
                              void* d_out, int out_size) {
    const float* h       = (const float*)d_in[0];
    const float* end_pos = (const float*)d_in[2];
    const float* rel_pos = (const float*)d_in[3];
    const float* Wenc    = (const float*)d_in[4];
    const float* benc    = (const float*)d_in[5];
    const float* Wdec    = (const float*)d_in[6];
    const float* bdec    = (const float*)d_in[7];
    const float* wfull   = (const float*)d_in[8];
    const float* bfull   = (const float*)d_in[9];
    const float* Wemb    = (const float*)d_in[10];
    const float* bemb    = (const float*)d_in[11];
    const float* Wout    = (const float*)d_in[12];
    const float* bout    = (const float*)d_in[13];
    const float* Wmlp    = (const float*)d_in[14];
    const float* bmlp    = (const float*)d_in[15];
    const float* gamma   = (const float*)d_in[16];
    const float* beta    = (const float*)d_in[17];
    float* out = (float*)d_out;

    float *p_dec, *p_x, *p_empty;
    __nv_bfloat16 *p_hAh, *p_hAl, *p_cAh, *p_cAl, *p_mAh, *p_mAl;
    __nv_bfloat16 *p_WdH, *p_WdL, *p_WoH, *p_WoL, *p_WmH, *p_WmL;
    cudaGetSymbolAddress((void**)&p_dec,   g_dec);
    cudaGetSymbolAddress((void**)&p_x,     g_x);
    cudaGetSymbolAddress((void**)&p_empty, g_empty);
    cudaGetSymbolAddress((void**)&p_hAh, g_hAh); cudaGetSymbolAddress((void**)&p_hAl, g_hAl);
    cudaGetSymbolAddress((void**)&p_cAh, g_cAh); cudaGetSymbolAddress((void**)&p_cAl, g_cAl);
    cudaGetSymbolAddress((void**)&p_mAh, g_mAh); cudaGetSymbolAddress((void**)&p_mAl, g_mAl);
    cudaGetSymbolAddress((void**)&p_WdH, g_WdH); cudaGetSymbolAddress((void**)&p_WdL, g_WdL);
    cudaGetSymbolAddress((void**)&p_WoH, g_WoH); cudaGetSymbolAddress((void**)&p_WoL, g_WoL);
    cudaGetSymbolAddress((void**)&p_WmH, g_WmH); cudaGetSymbolAddress((void**)&p_WmL, g_WmL);

    const int DSM = 2 * STAGEB;   // 147456
    cudaFuncSetAttribute(hm_gemm<0>, cudaFuncAttributeMaxDynamicSharedMemorySize, DSM);
    cudaFuncSetAttribute(hm_gemm<1>, cudaFuncAttributeMaxDynamicSharedMemorySize, DSM);
    cudaFuncSetAttribute(hm_gemm<2>, cudaFuncAttributeMaxDynamicSharedMemorySize, DSM);

    dim3 gg(8, 16);  // 1024/128 x 2048/128

    k_prep<<<8, 256>>>();
    k_splitA<<<(BQ * 64 + 255) / 256, 256>>>(h, p_hAh, p_hAl, BQ * 64);
    k_splitB<<<dim3(32, 2),  dim3(32, 8)>>>(Wdec, p_WdH, p_WdL, 64, 64);
    k_splitB<<<dim3(32, 4),  dim3(32, 8)>>>(Wout, p_WoH, p_WoL, 128, 68);
    k_splitB<<<dim3(32, 32), dim3(32, 8)>>>(Wmlp, p_WmH, p_WmL, 1024, 1024);
    k_pool<<<BQ, 256>>>(h, end_pos);
    hm_gemm<0><<<gg, 256, DSM>>>(p_hAh, p_hAl, p_WdH, p_WdL, bdec, 64,
                                 p_dec, nullptr, nullptr, benc, wfull, p_empty);
    k_scores<<<BQ, 256>>>(Wenc, benc, wfull, bfull);
    k_softctx<<<BQ, 128>>>(bfull, end_pos, rel_pos, Wemb, bemb);
    hm_gemm<1><<<gg, 256, DSM>>>(p_cAh, p_cAl, p_WoH, p_WoL, bout, 128,
                                 nullptr, p_mAh, p_mAl, nullptr, nullptr, nullptr);
    hm_gemm<2><<<gg, 256, DSM>>>(p_mAh, p_mAl, p_WmH, p_WmL, bmlp, 1024,
                                 p_x, nullptr, nullptr, nullptr, nullptr, nullptr);
    k_bnfinal<<<1, 1024>>>(gamma, beta);
    k_bnapply<<<(BQ * ATTD + 255) / 256, 256>>>(out);
}

// round 11
// speedup vs baseline: 1.9366x; 1.2759x over previous
#include <cuda_runtime.h>
#include <cuda_bf16.h>
#include <stdint.h>
#include <math.h>

#define BQ   2048
#define HD   64
#define ATTD 1024

typedef unsigned long long ull;

// ================= cp.async =================
__device__ __forceinline__ void cpasync16s(unsigned saddr, const void* g) {
    asm volatile("cp.async.cg.shared.global [%0], [%1], 16;" :: "r"(saddr), "l"(g));
}
__device__ __forceinline__ void cp_commit() { asm volatile("cp.async.commit_group;"); }
__device__ __forceinline__ void cp_wait0()  { asm volatile("cp.async.wait_group 0;"); }
__device__ __forceinline__ void cp_wait1()  { asm volatile("cp.async.wait_group 1;"); }

__device__ __forceinline__ unsigned smem_u32(const void* p) {
    return (unsigned)__cvta_generic_to_shared(p);
}

// ================= HMMA (mma.sync, baseline sm_80+ features) =================
#define LDSM4(r, a) asm volatile( \
    "ldmatrix.sync.aligned.m8n8.x4.shared.b16 {%0,%1,%2,%3}, [%4];" \
    : "=r"((r)[0]), "=r"((r)[1]), "=r"((r)[2]), "=r"((r)[3]) : "r"(a))

#define MMA16816(d, a, b) asm volatile( \
    "mma.sync.aligned.m16n8k16.row.col.f32.bf16.bf16.f32 " \
    "{%0,%1,%2,%3}, {%4,%5,%6,%7}, {%8,%9}, {%0,%1,%2,%3};" \
    : "+f"((d)[0]), "+f"((d)[1]), "+f"((d)[2]), "+f"((d)[3]) \
    : "r"((a)[0]), "r"((a)[1]), "r"((a)[2]), "r"((a)[3]), "r"((b)[0]), "r"((b)[1]))

// ================= device scratch =================
__device__ float g_dec[BQ * ATTD];
__device__ float g_encR[(size_t)BQ * 64 * HD];
__device__ int   g_rowb[BQ * 64];
__device__ int   g_base[BQ];
__device__ int   g_nnz[BQ];
__device__ float g_scoreR[BQ * 64];
__device__ int   g_R;
__device__ float g_empty[BQ];
__device__ float g_x[BQ * ATTD];
__device__ float g_bnsum[ATTD];
__device__ float g_bnsum2[ATTD];
__device__ float g_bna[ATTD];
__device__ float g_bnb[ATTD];
// bf16 split operands (16B aligned for cp.async)
__device__ __align__(16) __nv_bfloat16 g_hAh[BQ * 64],     g_hAl[BQ * 64];
__device__ __align__(16) __nv_bfloat16 g_cAh[BQ * 128],    g_cAl[BQ * 128];
__device__ __align__(16) __nv_bfloat16 g_mAh[BQ * 1024],   g_mAl[BQ * 1024];
__device__ __align__(16) __nv_bfloat16 g_WdH[1024 * 64],   g_WdL[1024 * 64];
__device__ __align__(16) __nv_bfloat16 g_WeH[1024 * 64],   g_WeL[1024 * 64];   // WencT
__device__ __align__(16) __nv_bfloat16 g_WoH[1024 * 128],  g_WoL[1024 * 128];
__device__ __align__(16) __nv_bfloat16 g_WmH[1024 * 1024], g_WmL[1024 * 1024];
__device__ __align__(16) __nv_bfloat16 g_eRh[(size_t)BQ * 64 * HD];             // encR hi
__device__ __align__(16) __nv_bfloat16 g_eRl[(size_t)BQ * 64 * HD];             // encR lo

// ================= prep =================
__global__ void k_prep() {
    int idx = blockIdx.x * blockDim.x + threadIdx.x;
    if (idx < ATTD) { g_bnsum[idx] = 0.f; g_bnsum2[idx] = 0.f; }
    if (idx < BQ) g_empty[idx] = 0.f;
    if (idx == 0) g_R = 0;
}

// ================= fp32 -> bf16 hi/lo split =================
__global__ void k_splitA(const float* __restrict__ A, __nv_bfloat16* __restrict__ Ah,
                         __nv_bfloat16* __restrict__ Al, int n) {
    int i = blockIdx.x * blockDim.x + threadIdx.x;
    if (i < n) {
        float v = A[i];
        __nv_bfloat16 hi = __float2bfloat16(v);
        Ah[i] = hi;
        Al[i] = __float2bfloat16(v - __bfloat162float(hi));
    }
}

// ======= weight split + transpose: W[KV<=KK rows][1024] -> Bt[1024][KK] =======
__global__ void k_splitB(const float* __restrict__ W, __nv_bfloat16* __restrict__ Bh,
                         __nv_bfloat16* __restrict__ Bl, int KK, int KV) {
    __shared__ float t[32][33];
    int n0 = blockIdx.x * 32, k0 = blockIdx.y * 32;
    int tx = threadIdx.x, ty = threadIdx.y;   // 32 x 8
#pragma unroll
    for (int i = 0; i < 4; i++) {
        int k = k0 + ty + i * 8;
        t[ty + i * 8][tx] = (k < KV) ? W[(size_t)k * 1024 + n0 + tx] : 0.f;
    }
    __syncthreads();
#pragma unroll
    for (int i = 0; i < 4; i++) {
        int n = n0 + ty + i * 8;
        float v = t[tx][ty + i * 8];
        __nv_bfloat16 hi = __float2bfloat16(v);
        Bh[(size_t)n * KK + k0 + tx] = hi;
        Bl[(size_t)n * KK + k0 + tx] = __float2bfloat16(v - __bfloat162float(hi));
    }
}

// ================= social pooling + compaction (emit fp32 + bf16 split) =======
__global__ void k_pool(const float* __restrict__ h, const float* __restrict__ end_pos) {
    int b = blockIdx.x;
    int s = b >> 6;
    int i = b & 63;
    int tid = threadIdx.x;      // 256
    int d = tid & 63;
    int g = tid >> 6;

    __shared__ __align__(16) float hsh[4096];
    __shared__ __align__(16) float acc[4096];
    __shared__ float px[64], py[64];
    __shared__ int   cellj[64];
    __shared__ int   nz[64];
    __shared__ int   slot_cell[64];
    __shared__ int   sh_base, sh_n;

    for (int t = tid; t < 1024; t += 256) {
        *(float4*)&hsh[t * 4] = *(const float4*)(h + (size_t)s * 4096 + t * 4);
        *(float4*)&acc[t * 4] = make_float4(0.f, 0.f, 0.f, 0.f);
    }
    if (tid < 64) {
        px[tid] = end_pos[(s * 64 + tid) * 2 + 0];
        py[tid] = end_pos[(s * 64 + tid) * 2 + 1];
        nz[tid] = 0;
    }
    __syncthreads();

    if (tid < 64) {
        float ax = px[i], ay = py[i];
        float tlx = ax - 1.0f, tly = ay + 1.0f;
        float brx = ax + 1.0f, bry = ay - 1.0f;
        float ox = px[tid], oy = py[tid];
        bool oob = (ox >= brx) || (ox <= tlx) || (oy >= tly) || (oy <= bry) || (tid == i);
        int c = -1;
        if (!oob) {
            float cx = floorf((ox - tlx) / 2.0f * 8.0f);
            float cy = floorf((tly - oy) / 2.0f * 8.0f);
            c = (int)(cx + cy * 8.0f);
        }
        cellj[tid] = c;
    }
    __syncthreads();

    for (int j = g * 16; j < g * 16 + 16; j++) {
        int c = cellj[j];
        if (c >= 0) {
            atomicAdd(&acc[c * 64 + d], hsh[j * 64 + d]);
            if (d == 0) nz[c] = 1;
        }
    }
    __syncthreads();

    if (tid == 0) {
        int n = 0;
        for (int c = 0; c < 64; c++) if (nz[c]) slot_cell[n++] = c;
        int base = atomicAdd(&g_R, n);
        sh_base = base; sh_n = n;
        g_base[b] = base; g_nnz[b] = n;
    }
    __syncthreads();

    int base = sh_base, n = sh_n;
    for (int t = g; t < n; t += 4) {
        int c = slot_cell[t];
        float v = acc[c * 64 + d];
        size_t off = (size_t)(base + t) * 64 + d;
        g_encR[off] = v;
        __nv_bfloat16 hi = __float2bfloat16(v);
        g_eRh[off] = hi;
        g_eRl[off] = __float2bfloat16(v - __bfloat162float(hi));
        if (d == 0) g_rowb[base + t] = b;
    }
}

// ================= HMMA bf16-split GEMM =================
// C[M,1024] = A[M,K] @ B[K,1024]; A hi/lo [M][K], Bt hi/lo [1024][K] (k-contig).
// CTA 128x128, 8 warps 2(M)x4(N), warp tile 64x32. K chunks of 64, 2-stage cp.async.
// EPI 0: f32 out + EMPTY (dec). EPI 1: relu -> bf16 hi/lo (out). EPI 2: f32 + BN (mlp).
#define RSTR  72                      // padded row stride, elements
#define MATB  (128 * RSTR * 2)        // 18432 B per matrix tile
#define STAGEB (4 * MATB)             // 73728 B per stage
template<int EPI>
__global__ void __launch_bounds__(256) hm_gemm(
    const __nv_bfloat16* __restrict__ Ah, const __nv_bfloat16* __restrict__ Al,
    const __nv_bfloat16* __restrict__ Bh, const __nv_bfloat16* __restrict__ Bl,
    const float* __restrict__ bias, int K,
    float* __restrict__ Cf,
    __nv_bfloat16* __restrict__ Coh, __nv_bfloat16* __restrict__ Col,
    const float* __restrict__ benc, const float* __restrict__ wfull,
    float* __restrict__ empty_out)
{
    extern __shared__ __align__(128) char dsm[];
    unsigned sbase = smem_u32(dsm);
    int tid = threadIdx.x;
    int lane = tid & 31, wid = tid >> 5;
    int m0 = blockIdx.y * 128, n0 = blockIdx.x * 128;
    int mb = (wid >> 2) * 64;
    int nb = (wid & 3) * 32;
    int NC = K >> 6;

    const __nv_bfloat16* gA_h = Ah + (size_t)m0 * K;
    const __nv_bfloat16* gA_l = Al + (size_t)m0 * K;
    const __nv_bfloat16* gB_h = Bh + (size_t)n0 * K;
    const __nv_bfloat16* gB_l = Bl + (size_t)n0 * K;

    auto stage_load = [&](int st, int kc) {
        unsigned so = sbase + st * STAGEB;
        const __nv_bfloat16* gs;
#pragma unroll
        for (int mat = 0; mat < 4; mat++) {
            gs = (mat == 0) ? gA_h : (mat == 1) ? gA_l : (mat == 2) ? gB_h : gB_l;
#pragma unroll
            for (int q = 0; q < 4; q++) {
                int idx = tid + q * 256;
                int r = idx >> 3, c = idx & 7;
                cpasync16s(so + mat * MATB + r * (RSTR * 2) + c * 16,
                           gs + (size_t)r * K + kc * 64 + c * 8);
            }
        }
    };

    float acc[4][4][4];
#pragma unroll
    for (int i = 0; i < 4; i++)
#pragma unroll
        for (int j = 0; j < 4; j++)
#pragma unroll
            for (int k = 0; k < 4; k++) acc[i][j][k] = 0.f;

    int quad = lane >> 3, rin = lane & 7;
    int a_r = (quad & 1) * 8 + rin;
    int a_c = (quad >> 1) * 8;
    int b_r = (quad >> 1) * 8 + rin;
    int b_c = (quad & 1) * 8;

    stage_load(0, 0);
    cp_commit();

    for (int ch = 0; ch < NC; ch++) {
        int st = ch & 1;
        if (ch + 1 < NC) { stage_load(st ^ 1, ch + 1); cp_commit(); cp_wait1(); }
        else cp_wait0();
        __syncthreads();
        unsigned so = sbase + st * STAGEB;

#pragma unroll
        for (int ks = 0; ks < 4; ks++) {
            unsigned fAh[4][4], fAl[4][4], fBh[2][4], fBl[2][4];
#pragma unroll
            for (int mt = 0; mt < 4; mt++) {
                unsigned ad = so + ((mb + mt * 16 + a_r) * RSTR + ks * 16 + a_c) * 2;
                LDSM4(fAh[mt], ad);
                LDSM4(fAl[mt], ad + MATB);
            }
#pragma unroll
            for (int np = 0; np < 2; np++) {
                unsigned bd = so + 2 * MATB + ((nb + np * 16 + b_r) * RSTR + ks * 16 + b_c) * 2;
                LDSM4(fBh[np], bd);
                LDSM4(fBl[np], bd + MATB);
            }
#pragma unroll
            for (int mt = 0; mt < 4; mt++)
#pragma unroll
                for (int nt = 0; nt < 4; nt++) {
                    unsigned* bh = &fBh[nt >> 1][(nt & 1) * 2];
                    unsigned* bl = &fBl[nt >> 1][(nt & 1) * 2];
                    MMA16816(acc[mt][nt], fAh[mt], bh);
                    MMA16816(acc[mt][nt], fAl[mt], bh);
                    MMA16816(acc[mt][nt], fAh[mt], bl);
                }
        }
        __syncthreads();
    }

    // ---- epilogue ----
    int g = lane >> 2;
    int cpos = (lane & 3) * 2;
    float cs[4][2], cq[4][2];
    if (EPI == 2) {
#pragma unroll
        for (int nt = 0; nt < 4; nt++) { cs[nt][0] = cs[nt][1] = 0.f; cq[nt][0] = cq[nt][1] = 0.f; }
    }

#pragma unroll
    for (int mt = 0; mt < 4; mt++) {
        int row = m0 + mb + mt * 16 + g;
        float e0 = 0.f, e1 = 0.f;
#pragma unroll
        for (int nt = 0; nt < 4; nt++) {
            int col = n0 + nb + nt * 8 + cpos;
            float b0v = bias[col], b1v = bias[col + 1];
            float v00 = acc[mt][nt][0] + b0v, v01 = acc[mt][nt][1] + b1v;
            float v10 = acc[mt][nt][2] + b0v, v11 = acc[mt][nt][3] + b1v;
            if (EPI == 1) {
                v00 = fmaxf(v00, 0.f); v01 = fmaxf(v01, 0.f);
                v10 = fmaxf(v10, 0.f); v11 = fmaxf(v11, 0.f);
                __nv_bfloat16 h00 = __float2bfloat16(v00), h01 = __float2bfloat16(v01);
                __nv_bfloat16 h10 = __float2bfloat16(v10), h11 = __float2bfloat16(v11);
                __nv_bfloat162 t;
                t.x = h00; t.y = h01;
                *(__nv_bfloat162*)&Coh[(size_t)row * 1024 + col] = t;
                t.x = h10; t.y = h11;
                *(__nv_bfloat162*)&Coh[(size_t)(row + 8) * 1024 + col] = t;
                t.x = __float2bfloat16(v00 - __bfloat162float(h00));
                t.y = __float2bfloat16(v01 - __bfloat162float(h01));
                *(__nv_bfloat162*)&Col[(size_t)row * 1024 + col] = t;
                t.x = __float2bfloat16(v10 - __bfloat162float(h10));
                t.y = __float2bfloat16(v11 - __bfloat162float(h11));
                *(__nv_bfloat162*)&Col[(size_t)(row + 8) * 1024 + col] = t;
            } else {
                float2 p;
                p.x = v00; p.y = v01;
                *(float2*)&Cf[(size_t)row * 1024 + col] = p;
                p.x = v10; p.y = v11;
                *(float2*)&Cf[(size_t)(row + 8) * 1024 + col] = p;
            }
            if (EPI == 0) {
                float be0 = benc[col], be1 = benc[col + 1];
                float wf0 = wfull[col], wf1 = wfull[col + 1];
                float t;
                t = v00 + be0; if (t > 0.f) e0 += t * wf0;
                t = v01 + be1; if (t > 0.f) e0 += t * wf1;
                t = v10 + be0; if (t > 0.f) e1 += t * wf0;
                t = v11 + be1; if (t > 0.f) e1 += t * wf1;
            }
            if (EPI == 2) {
                cs[nt][0] += v00 + v10; cs[nt][1] += v01 + v11;
                cq[nt][0] += v00 * v00 + v10 * v10;
                cq[nt][1] += v01 * v01 + v11 * v11;
            }
        }
        if (EPI == 0) {
            e0 += __shfl_xor_sync(0xffffffffu, e0, 1);
            e0 += __shfl_xor_sync(0xffffffffu, e0, 2);
            e1 += __shfl_xor_sync(0xffffffffu, e1, 1);
            e1 += __shfl_xor_sync(0xffffffffu, e1, 2);
            if ((lane & 3) == 0) {
                atomicAdd(&empty_out[row], e0);
                atomicAdd(&empty_out[row + 8], e1);
            }
        }
    }
    if (EPI == 2) {
#pragma unroll
        for (int nt = 0; nt < 4; nt++) {
#pragma unroll
            for (int j = 0; j < 2; j++) {
                float s = cs[nt][j], q = cq[nt][j];
                s += __shfl_xor_sync(0xffffffffu, s, 4);
                s += __shfl_xor_sync(0xffffffffu, s, 8);
                s += __shfl_xor_sync(0xffffffffu, s, 16);
                q += __shfl_xor_sync(0xffffffffu, q, 4);
                q += __shfl_xor_sync(0xffffffffu, q, 8);
                q += __shfl_xor_sync(0xffffffffu, q, 16);
                if (lane < 4) {
                    int col = n0 + nb + nt * 8 + cpos + j;
                    atomicAdd(&g_bnsum[col], s);
                    atomicAdd(&g_bnsum2[col], q);
                }
            }
        }
    }
}

// ================= HMMA sparse score GEMM =================
// rows r (compact): score[r] = sum_n relu(enc_r.Wenc[:,n] + benc[n] + dec[rowb[r],n]).wfull[n] + bfull
// CTA = 128 compact rows; loops over 8 N-tiles of 128. A (hi/lo) resident; Wenc-T streamed.
__global__ void __launch_bounds__(256) hm_scores(
    const __nv_bfloat16* __restrict__ WeH, const __nv_bfloat16* __restrict__ WeL,
    const float* __restrict__ benc, const float* __restrict__ wfull,
    const float* __restrict__ bfull)
{
    int R = g_R;
    int r0 = blockIdx.x * 128;
    if (r0 >= R) return;

    extern __shared__ __align__(128) char dsm[];
    unsigned sbase = smem_u32(dsm);
    // layout: [Ah][Al][Bst0_h][Bst0_l][Bst1_h][Bst1_l], each MATB
    __shared__ int   rb[128];
    __shared__ float red[128][5];

    int tid = threadIdx.x;
    int lane = tid & 31, wid = tid >> 5;
    int mb = (wid >> 2) * 64;
    int nw = wid & 3;
    int nb = nw * 32;

    if (tid < 128) rb[tid] = (r0 + tid < R) ? g_rowb[r0 + tid] : 0;

    // A load: 128 rows x 64 k, hi+lo (2048 16B chunks)
#pragma unroll
    for (int q = 0; q < 8; q++) {
        int idx = tid + q * 256;
        int mat = idx >> 10, r = (idx >> 3) & 127, c = idx & 7;
        const __nv_bfloat16* src = mat ? g_eRl : g_eRh;
        cpasync16s(sbase + mat * MATB + r * (RSTR * 2) + c * 16,
                   src + (size_t)(r0 + r) * 64 + c * 8);
    }
    auto stage_loadB = [&](int st, int nt) {
        unsigned so = sbase + 2 * MATB + st * 2 * MATB;
#pragma unroll
        for (int q = 0; q < 8; q++) {
            int idx = tid + q * 256;
            int mat = idx >> 10, r = (idx >> 3) & 127, c = idx & 7;
            const __nv_bfloat16* src = mat ? WeL : WeH;
            cpasync16s(so + mat * MATB + r * (RSTR * 2) + c * 16,
                       src + (size_t)(nt * 128 + r) * 64 + c * 8);
        }
    };
    stage_loadB(0, 0);
    cp_commit();

    int quad = lane >> 3, rin = lane & 7;
    int a_r = (quad & 1) * 8 + rin;
    int a_c = (quad >> 1) * 8;
    int b_r = (quad >> 1) * 8 + rin;
    int b_c = (quad & 1) * 8;
    int g = lane >> 2;
    int cpos = (lane & 3) * 2;

    float rs[4][2];
#pragma unroll
    for (int mt = 0; mt < 4; mt++) { rs[mt][0] = 0.f; rs[mt][1] = 0.f; }

    for (int ti = 0; ti < 8; ti++) {
        int st = ti & 1;
        if (ti + 1 < 8) { stage_loadB(st ^ 1, ti + 1); cp_commit(); cp_wait1(); }
        else cp_wait0();
        __syncthreads();
        unsigned bo = sbase + 2 * MATB + st * 2 * MATB;

        float acc[4][4][4];
#pragma unroll
        for (int i = 0; i < 4; i++)
#pragma unroll
            for (int j = 0; j < 4; j++)
#pragma unroll
                for (int k = 0; k < 4; k++) acc[i][j][k] = 0.f;

#pragma unroll
        for (int ks = 0; ks < 4; ks++) {
            unsigned fAh[4][4], fAl[4][4], fBh[2][4], fBl[2][4];
#pragma unroll
            for (int mt = 0; mt < 4; mt++) {
                unsigned ad = sbase + ((mb + mt * 16 + a_r) * RSTR + ks * 16 + a_c) * 2;
                LDSM4(fAh[mt], ad);
                LDSM4(fAl[mt], ad + MATB);
            }
#pragma unroll
            for (int np = 0; np < 2; np++) {
                unsigned bd = bo + ((nb + np * 16 + b_r) * RSTR + ks * 16 + b_c) * 2;
                LDSM4(fBh[np], bd);
                LDSM4(fBl[np], bd + MATB);
            }
#pragma unroll
            for (int mt = 0; mt < 4; mt++)
#pragma unroll
                for (int nt = 0; nt < 4; nt++) {
                    unsigned* bh = &fBh[nt >> 1][(nt & 1) * 2];
                    unsigned* bl = &fBl[nt >> 1][(nt & 1) * 2];
                    MMA16816(acc[mt][nt], fAh[mt], bh);
                    MMA16816(acc[mt][nt], fAl[mt], bh);
                    MMA16816(acc[mt][nt], fAh[mt], bl);
                }
        }

        // epilogue for this N-tile
#pragma unroll
        for (int nt = 0; nt < 4; nt++) {
            int col = ti * 128 + nb + nt * 8 + cpos;
            float be0 = benc[col], be1 = benc[col + 1];
            float wf0 = wfull[col], wf1 = wfull[col + 1];
#pragma unroll
            for (int mt = 0; mt < 4; mt++) {
                int rl0 = mb + mt * 16 + g;
                float2 d0 = *(const float2*)&g_dec[(size_t)rb[rl0] * 1024 + col];
                float2 d1 = *(const float2*)&g_dec[(size_t)rb[rl0 + 8] * 1024 + col];
                float v;
                v = acc[mt][nt][0] + be0 + d0.x; if (v > 0.f) rs[mt][0] += v * wf0;
                v = acc[mt][nt][1] + be1 + d0.y; if (v > 0.f) rs[mt][0] += v * wf1;
                v = acc[mt][nt][2] + be0 + d1.x; if (v > 0.f) rs[mt][1] += v * wf0;
                v = acc[mt][nt][3] + be1 + d1.y; if (v > 0.f) rs[mt][1] += v * wf1;
            }
        }
        __syncthreads();
    }

    // reduce: lanes within quad, then across the 4 N-warps
#pragma unroll
    for (int mt = 0; mt < 4; mt++) {
#pragma unroll
        for (int hh = 0; hh < 2; hh++) {
            float r = rs[mt][hh];
            r += __shfl_xor_sync(0xffffffffu, r, 1);
            r += __shfl_xor_sync(0xffffffffu, r, 2);
            if ((lane & 3) == 0) red[mb + mt * 16 + g + hh * 8][nw] = r;
        }
    }
    __syncthreads();
    if (tid < 128 && r0 + tid < R) {
        g_scoreR[r0 + tid] = red[tid][0] + red[tid][1] + red[tid][2] + red[tid][3] + bfull[0];
    }
}

// ================= softmax + ctx + embed -> bf16 split A for out-GEMM =========
__global__ void k_softctx(const float* __restrict__ bfull, const float* __restrict__ end_pos,
                          const float* __restrict__ rel_pos, const float* __restrict__ Wemb,
                          const float* __restrict__ bemb) {
    int b = blockIdx.x;
    int tid = threadIdx.x;  // 128
    __shared__ float sc[64];
    __shared__ float alpha[64];

    int base = g_base[b], nnz = g_nnz[b];
    if (tid < nnz) sc[tid] = g_scoreR[base + tid];
    __syncthreads();
    if (tid == 0) {
        float se = g_empty[b] + bfull[0];
        float m = se;
        for (int t = 0; t < nnz; t++) m = fmaxf(m, sc[t]);
        float Z = (float)(64 - nnz) * expf(se - m);
        for (int t = 0; t < nnz; t++) { float e = expf(sc[t] - m); alpha[t] = e; Z += e; }
        float inv = 1.0f / Z;
        for (int t = 0; t < nnz; t++) alpha[t] *= inv;
    }
    __syncthreads();

    float v = 0.f;
    if (tid < 64) {
        float c = 0.f;
        for (int t = 0; t < nnz; t++) c += alpha[t] * g_encR[(size_t)(base + t) * 64 + tid];
        v = c;
    } else if (tid < 68) {
        int j = tid - 64;
        float e = end_pos[b * 2 + 0] * Wemb[0 * 4 + j] + end_pos[b * 2 + 1] * Wemb[1 * 4 + j]
                + rel_pos[b * 2 + 0] * Wemb[2 * 4 + j] + rel_pos[b * 2 + 1] * Wemb[3 * 4 + j]
                + bemb[j];
        v = fmaxf(e, 0.f);
    }
    __nv_bfloat16 hi = __float2bfloat16(v);
    g_cAh[b * 128 + tid] = hi;
    g_cAl[b * 128 + tid] = __float2bfloat16(v - __bfloat162float(hi));
}

// ================= batchnorm final + apply =================
__global__ void k_bnfinal(const float* __restrict__ gamma, const float* __restrict__ beta) {
    int c = threadIdx.x;
    float mu = g_bnsum[c] / (float)BQ;
    float var = g_bnsum2[c] / (float)BQ - mu * mu;
    float rstd = rsqrtf(var + 1e-5f);
    float ga = gamma[c] * rstd;
    g_bna[c] = ga;
    g_bnb[c] = beta[c] - mu * ga;
}

__global__ void k_bnapply(float* __restrict__ out) {
    int idx = blockIdx.x * blockDim.x + threadIdx.x;
    if (idx < BQ * ATTD) {
        int c = idx & 1023;
        float v = g_x[idx] * g_bna[c] + g_bnb[c];
        out[idx] = v > 0.f ? v : 0.f;
    }
}

// ================= launch =================
extern "C" void kernel_launch(void* const* d_in, const int* in_sizes, int n_in,
                              void* d_out, int out_size) {
    const float* h       = (const float*)d_in[0];
    const float* end_pos = (const float*)d_in[2];
    const float* rel_pos = (const float*)d_in[3];
    const float* Wenc    = (const float*)d_in[4];
    const float* benc    = (const float*)d_in[5];
    const float* Wdec    = (const float*)d_in[6];
    const float* bdec    = (const float*)d_in[7];
    const float* wfull   = (const float*)d_in[8];
    const float* bfull   = (const float*)d_in[9];
    const float* Wemb    = (const float*)d_in[10];
    const float* bemb    = (const float*)d_in[11];
    const float* Wout    = (const float*)d_in[12];
    const float* bout    = (const float*)d_in[13];
    const float* Wmlp    = (const float*)d_in[14];
    const float* bmlp    = (const float*)d_in[15];
    const float* gamma   = (const float*)d_in[16];
    const float* beta    = (const float*)d_in[17];
    float* out = (float*)d_out;

    float *p_dec, *p_x, *p_empty;
    __nv_bfloat16 *p_hAh, *p_hAl, *p_cAh, *p_cAl, *p_mAh, *p_mAl;
    __nv_bfloat16 *p_WdH, *p_WdL, *p_WeH, *p_WeL, *p_WoH, *p_WoL, *p_WmH, *p_WmL;
    cudaGetSymbolAddress((void**)&p_dec,   g_dec);
    cudaGetSymbolAddress((void**)&p_x,     g_x);
    cudaGetSymbolAddress((void**)&p_empty, g_empty);
    cudaGetSymbolAddress((void**)&p_hAh, g_hAh); cudaGetSymbolAddress((void**)&p_hAl, g_hAl);
    cudaGetSymbolAddress((void**)&p_cAh, g_cAh); cudaGetSymbolAddress((void**)&p_cAl, g_cAl);
    cudaGetSymbolAddress((void**)&p_mAh, g_mAh); cudaGetSymbolAddress((void**)&p_mAl, g_mAl);
    cudaGetSymbolAddress((void**)&p_WdH, g_WdH); cudaGetSymbolAddress((void**)&p_WdL, g_WdL);
    cudaGetSymbolAddress((void**)&p_WeH, g_WeH); cudaGetSymbolAddress((void**)&p_WeL, g_WeL);
    cudaGetSymbolAddress((void**)&p_WoH, g_WoH); cudaGetSymbolAddress((void**)&p_WoL, g_WoL);
    cudaGetSymbolAddress((void**)&p_WmH, g_WmH); cudaGetSymbolAddress((void**)&p_WmL, g_WmL);

    const int DSM  = 2 * STAGEB;     // 147456 (hm_gemm)
    const int DSMS = 6 * MATB;       // 110592 (hm_scores)
    cudaFuncSetAttribute(hm_gemm<0>, cudaFuncAttributeMaxDynamicSharedMemorySize, DSM);
    cudaFuncSetAttribute(hm_gemm<1>, cudaFuncAttributeMaxDynamicSharedMemorySize, DSM);
    cudaFuncSetAttribute(hm_gemm<2>, cudaFuncAttributeMaxDynamicSharedMemorySize, DSM);
    cudaFuncSetAttribute(hm_scores,  cudaFuncAttributeMaxDynamicSharedMemorySize, DSMS);

    dim3 gg(8, 16);  // 1024/128 x 2048/128

    k_prep<<<8, 256>>>();
    k_splitA<<<(BQ * 64 + 255) / 256, 256>>>(h, p_hAh, p_hAl, BQ * 64);
    k_splitB<<<dim3(32, 2),  dim3(32, 8)>>>(Wdec, p_WdH, p_WdL, 64, 64);
    k_splitB<<<dim3(32, 2),  dim3(32, 8)>>>(Wenc, p_WeH, p_WeL, 64, 64);
    k_splitB<<<dim3(32, 4),  dim3(32, 8)>>>(Wout, p_WoH, p_WoL, 128, 68);
    k_splitB<<<dim3(32, 32), dim3(32, 8)>>>(Wmlp, p_WmH, p_WmL, 1024, 1024);
    k_pool<<<BQ, 256>>>(h, end_pos);
    hm_gemm<0><<<gg, 256, DSM>>>(p_hAh, p_hAl, p_WdH, p_WdL, bdec, 64,
                                 p_dec, nullptr, nullptr, benc, wfull, p_empty);
    hm_scores<<<BQ * 64 / 128, 256, DSMS>>>(p_WeH, p_WeL, benc, wfull, bfull);
    k_softctx<<<BQ, 128>>>(bfull, end_pos, rel_pos, Wemb, bemb);
    hm_gemm<1><<<gg, 256, DSM>>>(p_cAh, p_cAl, p_WoH, p_WoL, bout, 128,
                                 nullptr, p_mAh, p_mAl, nullptr, nullptr, nullptr);
    hm_gemm<2><<<gg, 256, DSM>>>(p_mAh, p_mAl, p_WmH, p_WmL, bmlp, 1024,
                                 p_x, nullptr, nullptr, nullptr, nullptr, nullptr);
    k_bnfinal<<<1, 1024>>>(gamma, beta);
    k_bnapply<<<(BQ * ATTD + 255) / 256, 256>>>(out);
}

// round 12
// speedup vs baseline: 2.0077x; 1.0367x over previous
#include <cuda_runtime.h>
#include <cuda_bf16.h>
#include <stdint.h>
#include <math.h>

#define BQ   2048
#define HD   64
#define ATTD 1024

typedef unsigned long long ull;

// ================= cp.async =================
__device__ __forceinline__ void cpasync16s(unsigned saddr, const void* g) {
    asm volatile("cp.async.cg.shared.global [%0], [%1], 16;" :: "r"(saddr), "l"(g));
}
__device__ __forceinline__ void cp_commit() { asm volatile("cp.async.commit_group;"); }
__device__ __forceinline__ void cp_wait0()  { asm volatile("cp.async.wait_group 0;"); }
__device__ __forceinline__ void cp_wait1()  { asm volatile("cp.async.wait_group 1;"); }

__device__ __forceinline__ unsigned smem_u32(const void* p) {
    return (unsigned)__cvta_generic_to_shared(p);
}

// ================= HMMA (mma.sync, baseline sm_80+ features) =================
#define LDSM4(r, a) asm volatile( \
    "ldmatrix.sync.aligned.m8n8.x4.shared.b16 {%0,%1,%2,%3}, [%4];" \
    : "=r"((r)[0]), "=r"((r)[1]), "=r"((r)[2]), "=r"((r)[3]) : "r"(a))

#define MMA16816(d, a, b) asm volatile( \
    "mma.sync.aligned.m16n8k16.row.col.f32.bf16.bf16.f32 " \
    "{%0,%1,%2,%3}, {%4,%5,%6,%7}, {%8,%9}, {%0,%1,%2,%3};" \
    : "+f"((d)[0]), "+f"((d)[1]), "+f"((d)[2]), "+f"((d)[3]) \
    : "r"((a)[0]), "r"((a)[1]), "r"((a)[2]), "r"((a)[3]), "r"((b)[0]), "r"((b)[1]))

// ================= device scratch =================
__device__ float g_dec[BQ * ATTD];
__device__ float g_encR[(size_t)BQ * 64 * HD];
__device__ int   g_rowb[BQ * 64];
__device__ int   g_base[BQ];
__device__ int   g_nnz[BQ];
__device__ float g_scoreR[BQ * 64];
__device__ int   g_R;
__device__ float g_empty[BQ];
__device__ float g_x[BQ * ATTD];
__device__ float g_bnsum[ATTD];
__device__ float g_bnsum2[ATTD];
__device__ float g_bna[ATTD];
__device__ float g_bnb[ATTD];
// bf16 split operands (16B aligned for cp.async)
__device__ __align__(16) __nv_bfloat16 g_hAh[BQ * 64],     g_hAl[BQ * 64];
__device__ __align__(16) __nv_bfloat16 g_cAh[BQ * 128],    g_cAl[BQ * 128];
__device__ __align__(16) __nv_bfloat16 g_mAh[BQ * 1024],   g_mAl[BQ * 1024];
__device__ __align__(16) __nv_bfloat16 g_WdH[1024 * 64],   g_WdL[1024 * 64];
__device__ __align__(16) __nv_bfloat16 g_WeH[1024 * 64],   g_WeL[1024 * 64];
__device__ __align__(16) __nv_bfloat16 g_WoH[1024 * 128],  g_WoL[1024 * 128];
__device__ __align__(16) __nv_bfloat16 g_WmH[1024 * 1024], g_WmL[1024 * 1024];
__device__ __align__(16) __nv_bfloat16 g_eRh[(size_t)BQ * 64 * HD];
__device__ __align__(16) __nv_bfloat16 g_eRl[(size_t)BQ * 64 * HD];

// ================= fused prologue: all splits + counter zeroing ==============
// blocks [0,64): Wdec  [64,128): Wenc  [128,256): Wout  [256,1280): Wmlp
// [1280,1792): splitA(h)  [1792,1800): zero counters
__device__ __forceinline__ void splitB_body(const float* __restrict__ W,
                                            __nv_bfloat16* __restrict__ Bh,
                                            __nv_bfloat16* __restrict__ Bl,
                                            int KK, int KV, int blk, int tid,
                                            float (*t)[33]) {
    int n0 = (blk & 31) * 32, k0 = (blk >> 5) * 32;
    int tx = tid & 31, ty = tid >> 5;   // 32 x 8
#pragma unroll
    for (int i = 0; i < 4; i++) {
        int k = k0 + ty + i * 8;
        t[ty + i * 8][tx] = (k < KV) ? W[(size_t)k * 1024 + n0 + tx] : 0.f;
    }
    __syncthreads();
#pragma unroll
    for (int i = 0; i < 4; i++) {
        int n = n0 + ty + i * 8;
        float v = t[tx][ty + i * 8];
        __nv_bfloat16 hi = __float2bfloat16(v);
        Bh[(size_t)n * KK + k0 + tx] = hi;
        Bl[(size_t)n * KK + k0 + tx] = __float2bfloat16(v - __bfloat162float(hi));
    }
}

__global__ void k_mega(const float* __restrict__ h,
                       const float* __restrict__ Wdec, const float* __restrict__ Wenc,
                       const float* __restrict__ Wout, const float* __restrict__ Wmlp) {
    __shared__ float t[32][33];
    int bid = blockIdx.x, tid = threadIdx.x;
    if (bid < 64) {
        splitB_body(Wdec, g_WdH, g_WdL, 64, 64, bid, tid, t);
    } else if (bid < 128) {
        splitB_body(Wenc, g_WeH, g_WeL, 64, 64, bid - 64, tid, t);
    } else if (bid < 256) {
        splitB_body(Wout, g_WoH, g_WoL, 128, 68, bid - 128, tid, t);
    } else if (bid < 1280) {
        splitB_body(Wmlp, g_WmH, g_WmL, 1024, 1024, bid - 256, tid, t);
    } else if (bid < 1792) {
        int i = (bid - 1280) * 256 + tid;     // < BQ*64 = 131072
        float v = h[i];
        __nv_bfloat16 hi = __float2bfloat16(v);
        g_hAh[i] = hi;
        g_hAl[i] = __float2bfloat16(v - __bfloat162float(hi));
    } else {
        int i = (bid - 1792) * 256 + tid;     // < 2048
        if (i < ATTD) { g_bnsum[i] = 0.f; g_bnsum2[i] = 0.f; }
        g_empty[i] = 0.f;
        if (i == 0) g_R = 0;
    }
}

// ================= social pooling + compaction (emit fp32 + bf16 split) =======
__global__ void k_pool(const float* __restrict__ h, const float* __restrict__ end_pos) {
    int b = blockIdx.x;
    int s = b >> 6;
    int i = b & 63;
    int tid = threadIdx.x;      // 256
    int d = tid & 63;
    int g = tid >> 6;

    __shared__ __align__(16) float hsh[4096];
    __shared__ __align__(16) float acc[4096];
    __shared__ float px[64], py[64];
    __shared__ int   cellj[64];
    __shared__ int   nz[64];
    __shared__ int   slot_cell[64];
    __shared__ int   sh_base, sh_n;

    for (int t = tid; t < 1024; t += 256) {
        *(float4*)&hsh[t * 4] = *(const float4*)(h + (size_t)s * 4096 + t * 4);
        *(float4*)&acc[t * 4] = make_float4(0.f, 0.f, 0.f, 0.f);
    }
    if (tid < 64) {
        px[tid] = end_pos[(s * 64 + tid) * 2 + 0];
        py[tid] = end_pos[(s * 64 + tid) * 2 + 1];
        nz[tid] = 0;
    }
    __syncthreads();

    if (tid < 64) {
        float ax = px[i], ay = py[i];
        float tlx = ax - 1.0f, tly = ay + 1.0f;
        float brx = ax + 1.0f, bry = ay - 1.0f;
        float ox = px[tid], oy = py[tid];
        bool oob = (ox >= brx) || (ox <= tlx) || (oy >= tly) || (oy <= bry) || (tid == i);
        int c = -1;
        if (!oob) {
            float cx = floorf((ox - tlx) / 2.0f * 8.0f);
            float cy = floorf((tly - oy) / 2.0f * 8.0f);
            c = (int)(cx + cy * 8.0f);
        }
        cellj[tid] = c;
    }
    __syncthreads();

    for (int j = g * 16; j < g * 16 + 16; j++) {
        int c = cellj[j];
        if (c >= 0) {
            atomicAdd(&acc[c * 64 + d], hsh[j * 64 + d]);
            if (d == 0) nz[c] = 1;
        }
    }
    __syncthreads();

    if (tid == 0) {
        int n = 0;
        for (int c = 0; c < 64; c++) if (nz[c]) slot_cell[n++] = c;
        int base = atomicAdd(&g_R, n);
        sh_base = base; sh_n = n;
        g_base[b] = base; g_nnz[b] = n;
    }
    __syncthreads();

    int base = sh_base, n = sh_n;
    for (int t = g; t < n; t += 4) {
        int c = slot_cell[t];
        float v = acc[c * 64 + d];
        size_t off = (size_t)(base + t) * 64 + d;
        g_encR[off] = v;
        __nv_bfloat16 hi = __float2bfloat16(v);
        g_eRh[off] = hi;
        g_eRl[off] = __float2bfloat16(v - __bfloat162float(hi));
        if (d == 0) g_rowb[base + t] = b;
    }
}

// ================= HMMA bf16-split GEMM =================
#define RSTR  72
#define MATB  (128 * RSTR * 2)
#define STAGEB (4 * MATB)
template<int EPI>
__global__ void __launch_bounds__(256) hm_gemm(
    const __nv_bfloat16* __restrict__ Ah, const __nv_bfloat16* __restrict__ Al,
    const __nv_bfloat16* __restrict__ Bh, const __nv_bfloat16* __restrict__ Bl,
    const float* __restrict__ bias, int K,
    float* __restrict__ Cf,
    __nv_bfloat16* __restrict__ Coh, __nv_bfloat16* __restrict__ Col,
    const float* __restrict__ benc, const float* __restrict__ wfull,
    float* __restrict__ empty_out)
{
    extern __shared__ __align__(128) char dsm[];
    unsigned sbase = smem_u32(dsm);
    int tid = threadIdx.x;
    int lane = tid & 31, wid = tid >> 5;
    int m0 = blockIdx.y * 128, n0 = blockIdx.x * 128;
    int mb = (wid >> 2) * 64;
    int nb = (wid & 3) * 32;
    int NC = K >> 6;

    const __nv_bfloat16* gA_h = Ah + (size_t)m0 * K;
    const __nv_bfloat16* gA_l = Al + (size_t)m0 * K;
    const __nv_bfloat16* gB_h = Bh + (size_t)n0 * K;
    const __nv_bfloat16* gB_l = Bl + (size_t)n0 * K;

    auto stage_load = [&](int st, int kc) {
        unsigned so = sbase + st * STAGEB;
        const __nv_bfloat16* gs;
#pragma unroll
        for (int mat = 0; mat < 4; mat++) {
            gs = (mat == 0) ? gA_h : (mat == 1) ? gA_l : (mat == 2) ? gB_h : gB_l;
#pragma unroll
            for (int q = 0; q < 4; q++) {
                int idx = tid + q * 256;
                int r = idx >> 3, c = idx & 7;
                cpasync16s(so + mat * MATB + r * (RSTR * 2) + c * 16,
                           gs + (size_t)r * K + kc * 64 + c * 8);
            }
        }
    };

    float acc[4][4][4];
#pragma unroll
    for (int i = 0; i < 4; i++)
#pragma unroll
        for (int j = 0; j < 4; j++)
#pragma unroll
            for (int k = 0; k < 4; k++) acc[i][j][k] = 0.f;

    int quad = lane >> 3, rin = lane & 7;
    int a_r = (quad & 1) * 8 + rin;
    int a_c = (quad >> 1) * 8;
    int b_r = (quad >> 1) * 8 + rin;
    int b_c = (quad & 1) * 8;

    stage_load(0, 0);
    cp_commit();

    for (int ch = 0; ch < NC; ch++) {
        int st = ch & 1;
        if (ch + 1 < NC) { stage_load(st ^ 1, ch + 1); cp_commit(); cp_wait1(); }
        else cp_wait0();
        __syncthreads();
        unsigned so = sbase + st * STAGEB;

#pragma unroll
        for (int ks = 0; ks < 4; ks++) {
            unsigned fAh[4][4], fAl[4][4], fBh[2][4], fBl[2][4];
#pragma unroll
            for (int mt = 0; mt < 4; mt++) {
                unsigned ad = so + ((mb + mt * 16 + a_r) * RSTR + ks * 16 + a_c) * 2;
                LDSM4(fAh[mt], ad);
                LDSM4(fAl[mt], ad + MATB);
            }
#pragma unroll
            for (int np = 0; np < 2; np++) {
                unsigned bd = so + 2 * MATB + ((nb + np * 16 + b_r) * RSTR + ks * 16 + b_c) * 2;
                LDSM4(fBh[np], bd);
                LDSM4(fBl[np], bd + MATB);
            }
#pragma unroll
            for (int mt = 0; mt < 4; mt++)
#pragma unroll
                for (int nt = 0; nt < 4; nt++) {
                    unsigned* bh = &fBh[nt >> 1][(nt & 1) * 2];
                    unsigned* bl = &fBl[nt >> 1][(nt & 1) * 2];
                    MMA16816(acc[mt][nt], fAh[mt], bh);
                    MMA16816(acc[mt][nt], fAl[mt], bh);
                    MMA16816(acc[mt][nt], fAh[mt], bl);
                }
        }
        __syncthreads();
    }

    // ---- epilogue ----
    int g = lane >> 2;
    int cpos = (lane & 3) * 2;
    float cs[4][2], cq[4][2];
    if (EPI == 2) {
#pragma unroll
        for (int nt = 0; nt < 4; nt++) { cs[nt][0] = cs[nt][1] = 0.f; cq[nt][0] = cq[nt][1] = 0.f; }
    }

#pragma unroll
    for (int mt = 0; mt < 4; mt++) {
        int row = m0 + mb + mt * 16 + g;
        float e0 = 0.f, e1 = 0.f;
#pragma unroll
        for (int nt = 0; nt < 4; nt++) {
            int col = n0 + nb + nt * 8 + cpos;
            float b0v = bias[col], b1v = bias[col + 1];
            float v00 = acc[mt][nt][0] + b0v, v01 = acc[mt][nt][1] + b1v;
            float v10 = acc[mt][nt][2] + b0v, v11 = acc[mt][nt][3] + b1v;
            if (EPI == 1) {
                v00 = fmaxf(v00, 0.f); v01 = fmaxf(v01, 0.f);
                v10 = fmaxf(v10, 0.f); v11 = fmaxf(v11, 0.f);
                __nv_bfloat16 h00 = __float2bfloat16(v00), h01 = __float2bfloat16(v01);
                __nv_bfloat16 h10 = __float2bfloat16(v10), h11 = __float2bfloat16(v11);
                __nv_bfloat162 t;
                t.x = h00; t.y = h01;
                *(__nv_bfloat162*)&Coh[(size_t)row * 1024 + col] = t;
                t.x = h10; t.y = h11;
                *(__nv_bfloat162*)&Coh[(size_t)(row + 8) * 1024 + col] = t;
                t.x = __float2bfloat16(v00 - __bfloat162float(h00));
                t.y = __float2bfloat16(v01 - __bfloat162float(h01));
                *(__nv_bfloat162*)&Col[(size_t)row * 1024 + col] = t;
                t.x = __float2bfloat16(v10 - __bfloat162float(h10));
                t.y = __float2bfloat16(v11 - __bfloat162float(h11));
                *(__nv_bfloat162*)&Col[(size_t)(row + 8) * 1024 + col] = t;
            } else {
                float2 p;
                p.x = v00; p.y = v01;
                *(float2*)&Cf[(size_t)row * 1024 + col] = p;
                p.x = v10; p.y = v11;
                *(float2*)&Cf[(size_t)(row + 8) * 1024 + col] = p;
            }
            if (EPI == 0) {
                float be0 = benc[col], be1 = benc[col + 1];
                float wf0 = wfull[col], wf1 = wfull[col + 1];
                float t;
                t = v00 + be0; if (t > 0.f) e0 += t * wf0;
                t = v01 + be1; if (t > 0.f) e0 += t * wf1;
                t = v10 + be0; if (t > 0.f) e1 += t * wf0;
                t = v11 + be1; if (t > 0.f) e1 += t * wf1;
            }
            if (EPI == 2) {
                cs[nt][0] += v00 + v10; cs[nt][1] += v01 + v11;
                cq[nt][0] += v00 * v00 + v10 * v10;
                cq[nt][1] += v01 * v01 + v11 * v11;
            }
        }
        if (EPI == 0) {
            e0 += __shfl_xor_sync(0xffffffffu, e0, 1);
            e0 += __shfl_xor_sync(0xffffffffu, e0, 2);
            e1 += __shfl_xor_sync(0xffffffffu, e1, 1);
            e1 += __shfl_xor_sync(0xffffffffu, e1, 2);
            if ((lane & 3) == 0) {
                atomicAdd(&empty_out[row], e0);
                atomicAdd(&empty_out[row + 8], e1);
            }
        }
    }
    if (EPI == 2) {
#pragma unroll
        for (int nt = 0; nt < 4; nt++) {
#pragma unroll
            for (int j = 0; j < 2; j++) {
                float s = cs[nt][j], q = cq[nt][j];
                s += __shfl_xor_sync(0xffffffffu, s, 4);
                s += __shfl_xor_sync(0xffffffffu, s, 8);
                s += __shfl_xor_sync(0xffffffffu, s, 16);
                q += __shfl_xor_sync(0xffffffffu, q, 4);
                q += __shfl_xor_sync(0xffffffffu, q, 8);
                q += __shfl_xor_sync(0xffffffffu, q, 16);
                if (lane < 4) {
                    int col = n0 + nb + nt * 8 + cpos + j;
                    atomicAdd(&g_bnsum[col], s);
                    atomicAdd(&g_bnsum2[col], q);
                }
            }
        }
    }
}

// ================= HMMA sparse score GEMM =================
__global__ void __launch_bounds__(256) hm_scores(
    const __nv_bfloat16* __restrict__ WeH, const __nv_bfloat16* __restrict__ WeL,
    const float* __restrict__ benc, const float* __restrict__ wfull,
    const float* __restrict__ bfull)
{
    int R = g_R;
    int r0 = blockIdx.x * 128;
    if (r0 >= R) return;

    extern __shared__ __align__(128) char dsm[];
    unsigned sbase = smem_u32(dsm);
    __shared__ int   rb[128];
    __shared__ float red[128][5];

    int tid = threadIdx.x;
    int lane = tid & 31, wid = tid >> 5;
    int mb = (wid >> 2) * 64;
    int nw = wid & 3;
    int nb = nw * 32;

    if (tid < 128) rb[tid] = (r0 + tid < R) ? g_rowb[r0 + tid] : 0;

#pragma unroll
    for (int q = 0; q < 8; q++) {
        int idx = tid + q * 256;
        int mat = idx >> 10, r = (idx >> 3) & 127, c = idx & 7;
        const __nv_bfloat16* src = mat ? g_eRl : g_eRh;
        cpasync16s(sbase + mat * MATB + r * (RSTR * 2) + c * 16,
                   src + (size_t)(r0 + r) * 64 + c * 8);
    }
    auto stage_loadB = [&](int st, int nt) {
        unsigned so = sbase + 2 * MATB + st * 2 * MATB;
#pragma unroll
        for (int q = 0; q < 8; q++) {
            int idx = tid + q * 256;
            int mat = idx >> 10, r = (idx >> 3) & 127, c = idx & 7;
            const __nv_bfloat16* src = mat ? WeL : WeH;
            cpasync16s(so + mat * MATB + r * (RSTR * 2) + c * 16,
                       src + (size_t)(nt * 128 + r) * 64 + c * 8);
        }
    };
    stage_loadB(0, 0);
    cp_commit();

    int quad = lane >> 3, rin = lane & 7;
    int a_r = (quad & 1) * 8 + rin;
    int a_c = (quad >> 1) * 8;
    int b_r = (quad >> 1) * 8 + rin;
    int b_c = (quad & 1) * 8;
    int g = lane >> 2;
    int cpos = (lane & 3) * 2;

    float rs[4][2];
#pragma unroll
    for (int mt = 0; mt < 4; mt++) { rs[mt][0] = 0.f; rs[mt][1] = 0.f; }

    for (int ti = 0; ti < 8; ti++) {
        int st = ti & 1;
        if (ti + 1 < 8) { stage_loadB(st ^ 1, ti + 1); cp_commit(); cp_wait1(); }
        else cp_wait0();
        __syncthreads();
        unsigned bo = sbase + 2 * MATB + st * 2 * MATB;

        float acc[4][4][4];
#pragma unroll
        for (int i = 0; i < 4; i++)
#pragma unroll
            for (int j = 0; j < 4; j++)
#pragma unroll
                for (int k = 0; k < 4; k++) acc[i][j][k] = 0.f;

#pragma unroll
        for (int ks = 0; ks < 4; ks++) {
            unsigned fAh[4][4], fAl[4][4], fBh[2][4], fBl[2][4];
#pragma unroll
            for (int mt = 0; mt < 4; mt++) {
                unsigned ad = sbase + ((mb + mt * 16 + a_r) * RSTR + ks * 16 + a_c) * 2;
                LDSM4(fAh[mt], ad);
                LDSM4(fAl[mt], ad + MATB);
            }
#pragma unroll
            for (int np = 0; np < 2; np++) {
                unsigned bd = bo + ((nb + np * 16 + b_r) * RSTR + ks * 16 + b_c) * 2;
                LDSM4(fBh[np], bd);
                LDSM4(fBl[np], bd + MATB);
            }
#pragma unroll
            for (int mt = 0; mt < 4; mt++)
#pragma unroll
                for (int nt = 0; nt < 4; nt++) {
                    unsigned* bh = &fBh[nt >> 1][(nt & 1) * 2];
                    unsigned* bl = &fBl[nt >> 1][(nt & 1) * 2];
                    MMA16816(acc[mt][nt], fAh[mt], bh);
                    MMA16816(acc[mt][nt], fAl[mt], bh);
                    MMA16816(acc[mt][nt], fAh[mt], bl);
                }
        }

#pragma unroll
        for (int nt = 0; nt < 4; nt++) {
            int col = ti * 128 + nb + nt * 8 + cpos;
            float be0 = benc[col], be1 = benc[col + 1];
            float wf0 = wfull[col], wf1 = wfull[col + 1];
#pragma unroll
            for (int mt = 0; mt < 4; mt++) {
                int rl0 = mb + mt * 16 + g;
                float2 d0 = *(const float2*)&g_dec[(size_t)rb[rl0] * 1024 + col];
                float2 d1 = *(const float2*)&g_dec[(size_t)rb[rl0 + 8] * 1024 + col];
                float v;
                v = acc[mt][nt][0] + be0 + d0.x; if (v > 0.f) rs[mt][0] += v * wf0;
                v = acc[mt][nt][1] + be1 + d0.y; if (v > 0.f) rs[mt][0] += v * wf1;
                v = acc[mt][nt][2] + be0 + d1.x; if (v > 0.f) rs[mt][1] += v * wf0;
                v = acc[mt][nt][3] + be1 + d1.y; if (v > 0.f) rs[mt][1] += v * wf1;
            }
        }
        __syncthreads();
    }

#pragma unroll
    for (int mt = 0; mt < 4; mt++) {
#pragma unroll
        for (int hh = 0; hh < 2; hh++) {
            float r = rs[mt][hh];
            r += __shfl_xor_sync(0xffffffffu, r, 1);
            r += __shfl_xor_sync(0xffffffffu, r, 2);
            if ((lane & 3) == 0) red[mb + mt * 16 + g + hh * 8][nw] = r;
        }
    }
    __syncthreads();
    if (tid < 128 && r0 + tid < R) {
        g_scoreR[r0 + tid] = red[tid][0] + red[tid][1] + red[tid][2] + red[tid][3] + bfull[0];
    }
}

// ================= softmax + ctx + embed -> bf16 split A for out-GEMM =========
__global__ void k_softctx(const float* __restrict__ bfull, const float* __restrict__ end_pos,
                          const float* __restrict__ rel_pos, const float* __restrict__ Wemb,
                          const float* __restrict__ bemb) {
    int b = blockIdx.x;
    int tid = threadIdx.x;  // 128
    __shared__ float sc[64];
    __shared__ float alpha[64];

    int base = g_base[b], nnz = g_nnz[b];
    if (tid < nnz) sc[tid] = g_scoreR[base + tid];
    __syncthreads();
    if (tid == 0) {
        float se = g_empty[b] + bfull[0];
        float m = se;
        for (int t = 0; t < nnz; t++) m = fmaxf(m, sc[t]);
        float Z = (float)(64 - nnz) * expf(se - m);
        for (int t = 0; t < nnz; t++) { float e = expf(sc[t] - m); alpha[t] = e; Z += e; }
        float inv = 1.0f / Z;
        for (int t = 0; t < nnz; t++) alpha[t] *= inv;
    }
    __syncthreads();

    float v = 0.f;
    if (tid < 64) {
        float c = 0.f;
        for (int t = 0; t < nnz; t++) c += alpha[t] * g_encR[(size_t)(base + t) * 64 + tid];
        v = c;
    } else if (tid < 68) {
        int j = tid - 64;
        float e = end_pos[b * 2 + 0] * Wemb[0 * 4 + j] + end_pos[b * 2 + 1] * Wemb[1 * 4 + j]
                + rel_pos[b * 2 + 0] * Wemb[2 * 4 + j] + rel_pos[b * 2 + 1] * Wemb[3 * 4 + j]
                + bemb[j];
        v = fmaxf(e, 0.f);
    }
    __nv_bfloat16 hi = __float2bfloat16(v);
    g_cAh[b * 128 + tid] = hi;
    g_cAl[b * 128 + tid] = __float2bfloat16(v - __bfloat162float(hi));
}

// ================= batchnorm final + apply =================
__global__ void k_bnfinal(const float* __restrict__ gamma, const float* __restrict__ beta) {
    int c = threadIdx.x;
    float mu = g_bnsum[c] / (float)BQ;
    float var = g_bnsum2[c] / (float)BQ - mu * mu;
    float rstd = rsqrtf(var + 1e-5f);
    float ga = gamma[c] * rstd;
    g_bna[c] = ga;
    g_bnb[c] = beta[c] - mu * ga;
}

__global__ void k_bnapply(float* __restrict__ out) {
    int idx = blockIdx.x * blockDim.x + threadIdx.x;
    if (idx < BQ * ATTD) {
        int c = idx & 1023;
        float v = g_x[idx] * g_bna[c] + g_bnb[c];
        out[idx] = v > 0.f ? v : 0.f;
    }
}

// ================= launch =================
extern "C" void kernel_launch(void* const* d_in, const int* in_sizes, int n_in,
                              void* d_out, int out_size) {
    const float* h       = (const float*)d_in[0];
    const float* end_pos = (const float*)d_in[2];
    const float* rel_pos = (const float*)d_in[3];
    const float* Wenc    = (const float*)d_in[4];
    const float* benc    = (const float*)d_in[5];
    const float* Wdec    = (const float*)d_in[6];
    const float* bdec    = (const float*)d_in[7];
    const float* wfull   = (const float*)d_in[8];
    const float* bfull   = (const float*)d_in[9];
    const float* Wemb    = (const float*)d_in[10];
    const float* bemb    = (const float*)d_in[11];
    const float* Wout    = (const float*)d_in[12];
    const float* bout    = (const float*)d_in[13];
    const float* Wmlp    = (const float*)d_in[14];
    const float* bmlp    = (const float*)d_in[15];
    const float* gamma   = (const float*)d_in[16];
    const float* beta    = (const float*)d_in[17];
    float* out = (float*)d_out;

    float *p_dec, *p_x, *p_empty;
    __nv_bfloat16 *p_hAh, *p_hAl, *p_cAh, *p_cAl, *p_mAh, *p_mAl;
    __nv_bfloat16 *p_WdH, *p_WdL, *p_WeH, *p_WeL, *p_WoH, *p_WoL, *p_WmH, *p_WmL;
    cudaGetSymbolAddress((void**)&p_dec,   g_dec);
    cudaGetSymbolAddress((void**)&p_x,     g_x);
    cudaGetSymbolAddress((void**)&p_empty, g_empty);
    cudaGetSymbolAddress((void**)&p_hAh, g_hAh); cudaGetSymbolAddress((void**)&p_hAl, g_hAl);
    cudaGetSymbolAddress((void**)&p_cAh, g_cAh); cudaGetSymbolAddress((void**)&p_cAl, g_cAl);
    cudaGetSymbolAddress((void**)&p_mAh, g_mAh); cudaGetSymbolAddress((void**)&p_mAl, g_mAl);
    cudaGetSymbolAddress((void**)&p_WdH, g_WdH); cudaGetSymbolAddress((void**)&p_WdL, g_WdL);
    cudaGetSymbolAddress((void**)&p_WeH, g_WeH); cudaGetSymbolAddress((void**)&p_WeL, g_WeL);
    cudaGetSymbolAddress((void**)&p_WoH, g_WoH); cudaGetSymbolAddress((void**)&p_WoL, g_WoL);
    cudaGetSymbolAddress((void**)&p_WmH, g_WmH); cudaGetSymbolAddress((void**)&p_WmL, g_WmL);

    const int DSM  = 2 * STAGEB;     // 147456 (hm_gemm)
    const int DSMS = 6 * MATB;       // 110592 (hm_scores)
    cudaFuncSetAttribute(hm_gemm<0>, cudaFuncAttributeMaxDynamicSharedMemorySize, DSM);
    cudaFuncSetAttribute(hm_gemm<1>, cudaFuncAttributeMaxDynamicSharedMemorySize, DSM);
    cudaFuncSetAttribute(hm_gemm<2>, cudaFuncAttributeMaxDynamicSharedMemorySize, DSM);
    cudaFuncSetAttribute(hm_scores,  cudaFuncAttributeMaxDynamicSharedMemorySize, DSMS);

    dim3 gg(8, 16);  // 1024/128 x 2048/128

    k_mega<<<1800, 256>>>(h, Wdec, Wenc, Wout, Wmlp);
    k_pool<<<BQ, 256>>>(h, end_pos);
    hm_gemm<0><<<gg, 256, DSM>>>(p_hAh, p_hAl, p_WdH, p_WdL, bdec, 64,
                                 p_dec, nullptr, nullptr, benc, wfull, p_empty);
    hm_scores<<<BQ * 64 / 128, 256, DSMS>>>(p_WeH, p_WeL, benc, wfull, bfull);
    k_softctx<<<BQ, 128>>>(bfull, end_pos, rel_pos, Wemb, bemb);
    hm_gemm<1><<<gg, 256, DSM>>>(p_cAh, p_cAl, p_WoH, p_WoL, bout, 128,
                                 nullptr, p_mAh, p_mAl, nullptr, nullptr, nullptr);
    hm_gemm<2><<<gg, 256, DSM>>>(p_mAh, p_mAl, p_WmH, p_WmL, bmlp, 1024,
                                 p_x, nullptr, nullptr, nullptr, nullptr, nullptr);
    k_bnfinal<<<1, 1024>>>(gamma, beta);
    k_bnapply<<<(BQ * ATTD + 255) / 256, 256>>>(out);
}